// round 2
// baseline (speedup 1.0000x reference)
#include <cuda_runtime.h>
#include <math.h>

#define B_      256
#define L_      16
#define H_      256
#define V_      5000
#define P_      4
#define NPG_    150
#define STEPS_  4
#define OUT_    2000
#define N_      (B_*NPG_)
#define E_      (N_*4)
#define BL_     (B_*L_)
#define LDLOG_  5008

static constexpr size_t SZ_C    = (size_t)(V_+1)*H_;
static constexpr size_t SZ_XW   = (size_t)BL_*H_;
static constexpr size_t SZ_LOG  = (size_t)BL_*LDLOG_;
static constexpr size_t SZ_VT   = (size_t)BL_*H_;
static constexpr size_t SZ_XG   = (size_t)BL_*4*H_;
static constexpr size_t SZ_G    = (size_t)B_*4*H_;
static constexpr size_t SZ_H    = (size_t)B_*H_;
static constexpr size_t SZ_HINS = (size_t)B_*STEPS_*H_;
static constexpr size_t SZ_TR   = (size_t)N_*3*H_;
static constexpr size_t SZ_ET   = (size_t)E_*H_;

static constexpr size_t OFF_C    = 0;
static constexpr size_t OFF_XW   = OFF_C    + SZ_C;
static constexpr size_t OFF_LOG  = OFF_XW   + SZ_XW;
static constexpr size_t OFF_RM   = OFF_LOG  + SZ_LOG;
static constexpr size_t OFF_RI   = OFF_RM   + BL_;
static constexpr size_t OFF_VT   = OFF_RI   + BL_;
static constexpr size_t OFF_XG   = OFF_VT   + SZ_VT;
static constexpr size_t OFF_G    = OFF_XG   + SZ_XG;
static constexpr size_t OFF_H    = OFF_G    + SZ_G;
static constexpr size_t OFF_CS   = OFF_H    + SZ_H;
static constexpr size_t OFF_HX   = OFF_CS   + SZ_H;
static constexpr size_t OFF_QW   = OFF_HX   + SZ_H;
static constexpr size_t OFF_HINS = OFF_QW   + SZ_H;
static constexpr size_t OFF_R    = OFF_HINS + SZ_HINS;
static constexpr size_t OFF_PS   = OFF_R    + SZ_HINS;
static constexpr size_t OFF_TR   = OFF_PS   + (size_t)B_*P_;
static constexpr size_t OFF_ET   = OFF_TR   + SZ_TR;
static constexpr size_t OFF_NS   = OFF_ET   + SZ_ET;
static constexpr size_t OFF_AGG  = OFF_NS   + N_;
static constexpr size_t OFF_DIST = OFF_AGG  + N_;
static constexpr size_t OFF_CNT  = OFF_DIST + N_;
static constexpr size_t OFF_AGR  = OFF_CNT  + B_;
static constexpr size_t OFF_QA   = OFF_AGR  + SZ_H;
static constexpr size_t TOTAL_SCRATCH = OFF_QA + (size_t)B_*2*H_;

__device__ __align__(16) float g_scratch[TOTAL_SCRATCH];

__device__ __forceinline__ float warp_sum(float v) {
    #pragma unroll
    for (int o = 16; o > 0; o >>= 1) v += __shfl_down_sync(0xffffffffu, v, o);
    return v;
}
__device__ __forceinline__ float sigmoidf_(float x) { return 1.f / (1.f + expf(-x)); }

// C[m,n] = sum_k A'[m,k] * (TRANSB ? B[n,k] : B[k,n]) (+bias[n]);
// A'[m,k] = EXPA ? exp(A[m,k]-rowmax[m])*rowinv[m] : A[m,k]
template<int BM, int BN, int TM, int TN, bool TRANSB, bool EXPA>
__global__ void __launch_bounds__((BM/TM)*(BN/TN))
gemm_k(const float* __restrict__ A, int lda,
       const float* __restrict__ Bm, int ldb,
       float* __restrict__ C, int ldc,
       int M, int N, int K,
       const float* __restrict__ bias,
       const float* __restrict__ rowmax,
       const float* __restrict__ rowinv)
{
    constexpr int BK = 8;
    constexpr int THREADS = (BM/TM)*(BN/TN);
    __shared__ float As[BK][BM];
    __shared__ float Bs[BK][BN];
    const int tid = threadIdx.x;
    const int bm = blockIdx.y * BM;
    const int bn = blockIdx.x * BN;
    const int tx = tid % (BN/TN);
    const int ty = tid / (BN/TN);
    float acc[TM][TN];
    #pragma unroll
    for (int i = 0; i < TM; i++)
        #pragma unroll
        for (int j = 0; j < TN; j++) acc[i][j] = 0.f;

    for (int k0 = 0; k0 < K; k0 += BK) {
        for (int it = tid; it < BM*2; it += THREADS) {
            int m  = it >> 1;
            int kq = (it & 1) * 4;
            int gm = bm + m;
            float4 v = make_float4(0.f, 0.f, 0.f, 0.f);
            if (gm < M) {
                v = *reinterpret_cast<const float4*>(A + (size_t)gm*lda + (k0 + kq));
                if (EXPA) {
                    float rm = rowmax[gm], ri = rowinv[gm];
                    v.x = expf(v.x - rm)*ri; v.y = expf(v.y - rm)*ri;
                    v.z = expf(v.z - rm)*ri; v.w = expf(v.w - rm)*ri;
                }
            }
            As[kq+0][m] = v.x; As[kq+1][m] = v.y;
            As[kq+2][m] = v.z; As[kq+3][m] = v.w;
        }
        if (TRANSB) {
            for (int it = tid; it < BN*2; it += THREADS) {
                int n  = it >> 1;
                int kq = (it & 1) * 4;
                int gn = bn + n;
                float4 v = make_float4(0.f, 0.f, 0.f, 0.f);
                if (gn < N) v = *reinterpret_cast<const float4*>(Bm + (size_t)gn*ldb + (k0 + kq));
                Bs[kq+0][n] = v.x; Bs[kq+1][n] = v.y;
                Bs[kq+2][n] = v.z; Bs[kq+3][n] = v.w;
            }
        } else {
            for (int it = tid; it < BN*2; it += THREADS) {
                int kr = it / (BN/4);
                int nq = (it % (BN/4)) * 4;
                const float* bp = Bm + (size_t)(k0 + kr)*ldb + bn + nq;
                float4 v;
                if (bn + nq + 3 < N) v = *reinterpret_cast<const float4*>(bp);
                else {
                    v.x = (bn+nq+0 < N) ? bp[0] : 0.f;
                    v.y = (bn+nq+1 < N) ? bp[1] : 0.f;
                    v.z = (bn+nq+2 < N) ? bp[2] : 0.f;
                    v.w = 0.f;
                }
                Bs[kr][nq+0] = v.x; Bs[kr][nq+1] = v.y;
                Bs[kr][nq+2] = v.z; Bs[kr][nq+3] = v.w;
            }
        }
        __syncthreads();
        #pragma unroll
        for (int k = 0; k < BK; k++) {
            float ar[TM], br[TN];
            #pragma unroll
            for (int i = 0; i < TM; i++) {
                int r = (i < TM/2) ? (ty*(TM/2) + i) : (BM/2 + ty*(TM/2) + (i - TM/2));
                ar[i] = As[k][r];
            }
            #pragma unroll
            for (int j = 0; j < TN; j++) {
                int c = (j < TN/2) ? (tx*(TN/2) + j) : (BN/2 + tx*(TN/2) + (j - TN/2));
                br[j] = Bs[k][c];
            }
            #pragma unroll
            for (int i = 0; i < TM; i++)
                #pragma unroll
                for (int j = 0; j < TN; j++)
                    acc[i][j] = fmaf(ar[i], br[j], acc[i][j]);
        }
        __syncthreads();
    }
    #pragma unroll
    for (int i = 0; i < TM; i++) {
        int r = (i < TM/2) ? (ty*(TM/2) + i) : (BM/2 + ty*(TM/2) + (i - TM/2));
        int gm = bm + r;
        if (gm >= M) continue;
        #pragma unroll
        for (int j = 0; j < TN; j++) {
            int c = (j < TN/2) ? (tx*(TN/2) + j) : (BN/2 + tx*(TN/2) + (j - TN/2));
            int gn = bn + c;
            if (gn >= N) continue;
            float v = acc[i][j];
            if (bias) v += bias[gn];
            C[(size_t)gm*ldc + gn] = v;
        }
    }
}

__global__ void build_c_k(const float* __restrict__ vocab, const float* __restrict__ de,
                          float* __restrict__ Cc) {
    int i = blockIdx.x*256 + threadIdx.x;
    if (i < (V_+1)*H_) Cc[i] = (i < V_*H_) ? vocab[i] : de[i - (size_t)V_*H_];
}

__global__ void zero_k(float* __restrict__ p, int n) {
    int i = blockIdx.x*256 + threadIdx.x;
    if (i < n) p[i] = 0.f;
}

__global__ void row_softmax_k(const float* __restrict__ Lg, float* __restrict__ rm,
                              float* __restrict__ ri) {
    int r = blockIdx.x;
    const float* row = Lg + (size_t)r*LDLOG_;
    float m = -3.4e38f, s = 0.f;
    for (int j = threadIdx.x; j < V_+1; j += 256) {
        float x = row[j];
        float nm = fmaxf(m, x);
        s = s*expf(m - nm) + expf(x - nm);
        m = nm;
    }
    __shared__ float sm[256], ss[256];
    sm[threadIdx.x] = m; ss[threadIdx.x] = s;
    __syncthreads();
    for (int o = 128; o > 0; o >>= 1) {
        if (threadIdx.x < o) {
            float m2 = sm[threadIdx.x+o], s2 = ss[threadIdx.x+o];
            float M2 = fmaxf(sm[threadIdx.x], m2);
            ss[threadIdx.x] = ss[threadIdx.x]*expf(sm[threadIdx.x]-M2) + s2*expf(m2-M2);
            sm[threadIdx.x] = M2;
        }
        __syncthreads();
    }
    if (threadIdx.x == 0) { rm[r] = sm[0]; ri[r] = 1.f/ss[0]; }
}

__global__ void vtag_eps_k(const float* __restrict__ words, const float* __restrict__ Lg,
                           const float* __restrict__ rm, const float* __restrict__ ri,
                           float* __restrict__ Vt) {
    int i = blockIdx.x*256 + threadIdx.x;
    int r = i >> 8;
    float w = expf(Lg[(size_t)r*LDLOG_ + V_] - rm[r]) * ri[r];
    Vt[i] += w * words[i];
}

__global__ void lstm_gates_k(const float* __restrict__ Xg, const float* __restrict__ Hg,
                             const int* __restrict__ lengths, int t,
                             float* __restrict__ h, float* __restrict__ c) {
    int i = blockIdx.x*256 + threadIdx.x;
    int b = i >> 8, hh = i & 255;
    if (t >= lengths[b]) return;
    const float* xrow = Xg + (size_t)(b*L_ + t)*(4*H_);
    const float* grow = Hg + (size_t)b*(4*H_);
    float gi = xrow[hh]        + grow[hh];
    float gf = xrow[H_ + hh]   + grow[H_ + hh];
    float gc = xrow[2*H_ + hh] + grow[2*H_ + hh];
    float go = xrow[3*H_ + hh] + grow[3*H_ + hh];
    float cn = sigmoidf_(gf)*c[i] + sigmoidf_(gi)*tanhf(gc);
    c[i] = cn;
    h[i] = sigmoidf_(go)*tanhf(cn);
}

__global__ void dec_step_k(const float* __restrict__ Qw, const float* __restrict__ Whh,
                           const float* __restrict__ bhh, int step,
                           float* __restrict__ hx, float* __restrict__ Hins) {
    int b = blockIdx.x, h = threadIdx.x;
    __shared__ float sh[H_];
    sh[h] = hx[b*H_ + h];
    __syncthreads();
    float acc = Qw[b*H_ + h] + bhh[h];
    const float* wr = Whh + (size_t)h*H_;
    #pragma unroll 8
    for (int k = 0; k < H_; k++) acc = fmaf(sh[k], wr[k], acc);
    acc = fmaxf(acc, 0.f);
    hx[b*H_ + h] = acc;
    Hins[((size_t)b*STEPS_ + step)*H_ + h] = acc;
}

__global__ void attention_k(const float* __restrict__ Vt, const float* __restrict__ Hins,
                            const int* __restrict__ lengths, float* __restrict__ R) {
    int b = blockIdx.x, tid = threadIdx.x;
    __shared__ float sV[L_][H_];
    __shared__ float sH[STEPS_][H_];
    __shared__ float satt[STEPS_][L_];
    for (int i = tid; i < L_*H_; i += 256)      sV[i>>8][i&255] = Vt[(size_t)b*L_*H_ + i];
    for (int i = tid; i < STEPS_*H_; i += 256)  sH[i>>8][i&255] = Hins[(size_t)b*STEPS_*H_ + i];
    __syncthreads();
    int warp = tid >> 5, lane = tid & 31;
    for (int pid = warp; pid < STEPS_*L_; pid += 8) {
        int s = pid >> 4, l = pid & 15;
        float a = 0.f;
        #pragma unroll
        for (int q = 0; q < H_/32; q++) a = fmaf(sH[s][lane + 32*q], sV[l][lane + 32*q], a);
        a = warp_sum(a);
        if (lane == 0) satt[s][l] = a;
    }
    __syncthreads();
    if (tid < STEPS_) {
        int len = lengths[b];
        float m = -3.4e38f;
        for (int l = 0; l < len; l++) m = fmaxf(m, satt[tid][l]);
        float s = 0.f;
        for (int l = 0; l < len; l++) { float e = expf(satt[tid][l] - m); satt[tid][l] = e; s += e; }
        float inv = 1.f/s;
        for (int l = 0; l < L_; l++) satt[tid][l] = (l < len) ? satt[tid][l]*inv : 0.f;
    }
    __syncthreads();
    for (int s = 0; s < STEPS_; s++) {
        float acc = 0.f;
        #pragma unroll
        for (int l = 0; l < L_; l++) acc = fmaf(satt[s][l], sV[l][tid], acc);
        R[((size_t)b*STEPS_ + s)*H_ + tid] = acc;
    }
}

__global__ void count_nodes_k(const int* __restrict__ ng, int* __restrict__ cnt) {
    int i = blockIdx.x*256 + threadIdx.x;
    if (i < N_) atomicAdd(&cnt[ng[i]], 1);
}
__global__ void init_dist_k(const int* __restrict__ ng, const int* __restrict__ cnt,
                            float* __restrict__ dist) {
    int i = blockIdx.x*256 + threadIdx.x;
    if (i < N_) dist[i] = 1.f/(float)cnt[ng[i]];
}

__global__ void prop_softmax_k(const float* __restrict__ R, int step,
                               const float* __restrict__ pe, float* __restrict__ ps) {
    int b = blockIdx.x;
    int p = threadIdx.x >> 5, lane = threadIdx.x & 31;
    const float* instr = R + ((size_t)b*STEPS_ + step)*H_;
    float acc = 0.f;
    for (int h = lane; h < H_; h += 32) acc = fmaf(instr[h], pe[p*H_ + h], acc);
    acc = warp_sum(acc);
    __shared__ float s4[P_];
    if (lane == 0) s4[p] = acc;
    __syncthreads();
    if (threadIdx.x == 0) {
        float m = fmaxf(fmaxf(s4[0], s4[1]), fmaxf(s4[2], s4[3]));
        float e0 = expf(s4[0]-m), e1 = expf(s4[1]-m), e2 = expf(s4[2]-m), e3 = expf(s4[3]-m);
        float inv = 1.f/(e0+e1+e2+e3);
        ps[b*P_+0] = e0*inv; ps[b*P_+1] = e1*inv; ps[b*P_+2] = e2*inv; ps[b*P_+3] = e3*inv;
    }
}

__global__ void node_pass_k(const float* __restrict__ Tr, const float* __restrict__ R, int step,
                            const float* __restrict__ ps, const float* __restrict__ Wst,
                            const int* __restrict__ ng, float* __restrict__ nst) {
    int n = (blockIdx.x*blockDim.x + threadIdx.x) >> 5;
    int lane = threadIdx.x & 31;
    if (n >= N_) return;
    int g = ng[n];
    const float* instr = R + ((size_t)g*STEPS_ + step)*H_;
    float p0 = ps[g*P_+0], p1 = ps[g*P_+1], p2 = ps[g*P_+2];
    const float* T = Tr + (size_t)n*3*H_;
    float acc = 0.f;
    #pragma unroll
    for (int q = 0; q < H_/32; q++) {
        int h = lane + 32*q;
        float tv = p0*T[h] + p1*T[H_+h] + p2*T[2*H_+h];
        float x = instr[h]*tv;
        float e = (x > 0.f) ? x : expm1f(x);
        acc = fmaf(e, Wst[h], acc);
    }
    acc = warp_sum(acc);
    if (lane == 0) nst[n] = acc;
}

__global__ void edge_pass_k(const float* __restrict__ Et, const float* __restrict__ R, int step,
                            const float* __restrict__ Wrel,
                            const int* __restrict__ eg, const int* __restrict__ esrc,
                            const int* __restrict__ edst,
                            const float* __restrict__ dist, float* __restrict__ agg) {
    int e = (blockIdx.x*blockDim.x + threadIdx.x) >> 5;
    int lane = threadIdx.x & 31;
    if (e >= E_) return;
    int g = eg[e];
    const float* instr = R + ((size_t)g*STEPS_ + step)*H_;
    const float* et = Et + (size_t)e*H_;
    float acc = 0.f;
    #pragma unroll
    for (int q = 0; q < H_/32; q++) {
        int h = lane + 32*q;
        float x = instr[h]*et[h];
        float el = (x > 0.f) ? x : expm1f(x);
        acc = fmaf(el, Wrel[h], acc);
    }
    acc = warp_sum(acc);
    if (lane == 0) atomicAdd(&agg[edst[e]], dist[esrc[e]]*acc);
}

__global__ void seg_update_k(const float* __restrict__ nst, const float* __restrict__ agg,
                             const float* __restrict__ ps, float* __restrict__ dist) {
    int g = blockIdx.x, tid = threadIdx.x;
    __shared__ float red[256];
    float v1 = (tid < NPG_) ? nst[g*NPG_ + tid] : -3.4e38f;
    float v2 = (tid < NPG_) ? agg[g*NPG_ + tid] : -3.4e38f;
    red[tid] = v1; __syncthreads();
    for (int o = 128; o > 0; o >>= 1) { if (tid < o) red[tid] = fmaxf(red[tid], red[tid+o]); __syncthreads(); }
    float m1 = red[0]; __syncthreads();
    red[tid] = v2; __syncthreads();
    for (int o = 128; o > 0; o >>= 1) { if (tid < o) red[tid] = fmaxf(red[tid], red[tid+o]); __syncthreads(); }
    float m2 = red[0]; __syncthreads();
    float e1 = (tid < NPG_) ? expf(v1 - m1) : 0.f;
    float e2 = (tid < NPG_) ? expf(v2 - m2) : 0.f;
    red[tid] = e1; __syncthreads();
    for (int o = 128; o > 0; o >>= 1) { if (tid < o) red[tid] += red[tid+o]; __syncthreads(); }
    float s1 = red[0]; __syncthreads();
    red[tid] = e2; __syncthreads();
    for (int o = 128; o > 0; o >>= 1) { if (tid < o) red[tid] += red[tid+o]; __syncthreads(); }
    float s2 = red[0];
    if (tid < NPG_) {
        float r = ps[g*P_ + 3];
        dist[g*NPG_ + tid] = r*(e2/s2) + (1.f - r)*(e1/s1);
    }
}

__global__ void final_agg_k(const float* __restrict__ na, const float* __restrict__ ps,
                            const float* __restrict__ dist, float* __restrict__ agr) {
    int g = blockIdx.x, h = threadIdx.x;
    float p0 = ps[g*P_], p1 = ps[g*P_+1], p2 = ps[g*P_+2];
    float acc = 0.f;
    for (int i = 0; i < NPG_; i++) {
        size_t n = (size_t)g*NPG_ + i;
        const float* a = na + n*3*H_;
        float nf = p0*a[h] + p1*a[H_+h] + p2*a[2*H_+h];
        acc = fmaf(dist[n], nf, acc);
    }
    agr[g*H_ + h] = acc;
}

__global__ void build_qa_k(const float* __restrict__ Q, const float* __restrict__ agr,
                           float* __restrict__ QA) {
    int i = blockIdx.x*256 + threadIdx.x;
    int b = i >> 9, k = i & 511;
    QA[i] = (k < H_) ? Q[b*H_ + k] : agr[b*H_ + (k - H_)];
}

static inline void gemm128_nt(const float* A, int lda, const float* Bm, int ldb,
                              float* C, int ldc, int M, int N, int K, const float* bias) {
    dim3 g((N + 127)/128, (M + 127)/128);
    gemm_k<128,128,8,8,true,false><<<g, 256>>>(A, lda, Bm, ldb, C, ldc, M, N, K, bias, nullptr, nullptr);
}
static inline void gemm128_nn(const float* A, int lda, const float* Bm, int ldb,
                              float* C, int ldc, int M, int N, int K, const float* bias) {
    dim3 g((N + 127)/128, (M + 127)/128);
    gemm_k<128,128,8,8,false,false><<<g, 256>>>(A, lda, Bm, ldb, C, ldc, M, N, K, bias, nullptr, nullptr);
}
static inline void gemm128_nn_expa(const float* A, int lda, const float* Bm, int ldb,
                                   float* C, int ldc, int M, int N, int K,
                                   const float* rm, const float* ri) {
    dim3 g((N + 127)/128, (M + 127)/128);
    gemm_k<128,128,8,8,false,true><<<g, 256>>>(A, lda, Bm, ldb, C, ldc, M, N, K, nullptr, rm, ri);
}
static inline void gemm64_nt(const float* A, int lda, const float* Bm, int ldb,
                             float* C, int ldc, int M, int N, int K, const float* bias) {
    dim3 g((N + 63)/64, (M + 63)/64);
    gemm_k<64,64,4,4,true,false><<<g, 256>>>(A, lda, Bm, ldb, C, ldc, M, N, K, bias, nullptr, nullptr);
}

extern "C" void kernel_launch(void* const* d_in, const int* in_sizes, int n_in,
                              void* d_out, int out_size) {
    const float* questions     = (const float*)d_in[0];
    const float* node_attrs    = (const float*)d_in[1];
    const float* edge_attrs    = (const float*)d_in[2];
    const float* vocab         = (const float*)d_in[3];
    const float* default_embed = (const float*)d_in[4];
    const float* W_norm        = (const float*)d_in[5];
    const float* lstm_Wih      = (const float*)d_in[6];
    const float* lstm_Whh      = (const float*)d_in[7];
    const float* lstm_bih      = (const float*)d_in[8];
    const float* lstm_bhh      = (const float*)d_in[9];
    const float* rnn_Wih       = (const float*)d_in[10];
    const float* rnn_Whh       = (const float*)d_in[11];
    const float* rnn_bih       = (const float*)d_in[12];
    const float* rnn_bhh       = (const float*)d_in[13];
    const float* prop_embeds   = (const float*)d_in[14];
    const float* Ws_property   = (const float*)d_in[15];
    const float* W_state       = (const float*)d_in[16];
    const float* W_relation    = (const float*)d_in[17];
    const float* lin_W         = (const float*)d_in[18];
    const float* lin_b         = (const float*)d_in[19];
    const int*   lengths       = (const int*)d_in[20];
    const int*   node_graph    = (const int*)d_in[21];
    const int*   edge_graph    = (const int*)d_in[22];
    const int*   edge_src      = (const int*)d_in[23];
    const int*   edge_dst      = (const int*)d_in[24];
    float* out = (float*)d_out;

    float* S = nullptr;
    cudaGetSymbolAddress((void**)&S, g_scratch);
    float* Cc   = S + OFF_C;
    float* XW   = S + OFF_XW;
    float* LG   = S + OFF_LOG;
    float* RM   = S + OFF_RM;
    float* RI   = S + OFF_RI;
    float* VT   = S + OFF_VT;
    float* XG   = S + OFF_XG;
    float* G    = S + OFF_G;
    float* Hh   = S + OFF_H;
    float* HX   = S + OFF_HX;
    float* QW   = S + OFF_QW;
    float* HINS = S + OFF_HINS;
    float* Rr   = S + OFF_R;
    float* PS   = S + OFF_PS;
    float* TR   = S + OFF_TR;
    float* ET   = S + OFF_ET;
    float* NS   = S + OFF_NS;
    float* AGG  = S + OFF_AGG;
    float* DIST = S + OFF_DIST;
    int*   CNT  = (int*)(S + OFF_CNT);
    float* AGR  = S + OFF_AGR;
    float* QA   = S + OFF_QA;

    // 1. vocab tagging: C matrix, logits, softmax stats, Vtag
    build_c_k<<<((V_+1)*H_ + 255)/256, 256>>>(vocab, default_embed, Cc);
    gemm128_nn(questions, H_, W_norm, H_, XW, H_, BL_, H_, H_, nullptr);
    gemm128_nt(XW, H_, Cc, H_, LG, LDLOG_, BL_, V_+1, H_, nullptr);
    row_softmax_k<<<BL_, 256>>>(LG, RM, RI);
    gemm128_nn_expa(LG, LDLOG_, vocab, H_, VT, H_, BL_, H_, V_, RM, RI);
    vtag_eps_k<<<BL_*H_/256, 256>>>(questions, LG, RM, RI, VT);

    // 2. LSTM encoder
    gemm128_nt(VT, H_, lstm_Wih, H_, XG, 4*H_, BL_, 4*H_, H_, lstm_bih);
    zero_k<<<(2*B_*H_ + 255)/256, 256>>>(Hh, 2*B_*H_);   // h and c (contiguous)
    for (int t = 0; t < L_; t++) {
        gemm64_nt(Hh, H_, lstm_Whh, H_, G, 4*H_, B_, 4*H_, H_, lstm_bhh);
        lstm_gates_k<<<B_*H_/256, 256>>>(XG, G, lengths, t, Hh, S + OFF_CS);
    }

    // 3. decoder RNN + attention
    gemm64_nt(Hh, H_, rnn_Wih, H_, QW, H_, B_, H_, H_, rnn_bih);
    zero_k<<<(B_*H_ + 255)/256, 256>>>(HX, B_*H_);
    for (int s = 0; s < STEPS_; s++)
        dec_step_k<<<B_, H_>>>(QW, rnn_Whh, rnn_bhh, s, HX, HINS);
    attention_k<<<B_, 256>>>(VT, HINS, lengths, Rr);

    // 4. loop-invariant graph transforms
    for (int p = 0; p < 3; p++)
        gemm128_nt(node_attrs + p*H_, 3*H_, Ws_property + (size_t)p*H_*H_, H_,
                   TR + p*H_, 3*H_, N_, H_, H_, nullptr);
    gemm128_nt(edge_attrs, H_, Ws_property + (size_t)3*H_*H_, H_, ET, H_, E_, H_, H_, nullptr);

    zero_k<<<1, 256>>>((float*)CNT, B_);
    count_nodes_k<<<(N_ + 255)/256, 256>>>(node_graph, CNT);
    init_dist_k<<<(N_ + 255)/256, 256>>>(node_graph, CNT, DIST);

    // 5. 4 reasoning steps
    for (int s = 0; s < STEPS_; s++) {
        prop_softmax_k<<<B_, 128>>>(Rr, s, prop_embeds, PS);
        node_pass_k<<<N_*32/256, 256>>>(TR, Rr, s, PS, W_state, node_graph, NS);
        zero_k<<<(N_ + 255)/256, 256>>>(AGG, N_);
        edge_pass_k<<<E_*32/256, 256>>>(ET, Rr, s, W_relation, edge_graph, edge_src, edge_dst, DIST, AGG);
        seg_update_k<<<B_, 256>>>(NS, AGG, PS, DIST);
    }

    // 6. final aggregation + output projection
    final_agg_k<<<B_, 256>>>(node_attrs, PS, DIST, AGR);
    build_qa_k<<<B_*2*H_/256, 256>>>(Hh, AGR, QA);
    gemm128_nt(QA, 2*H_, lin_W, 2*H_, out, OUT_, B_, OUT_, 2*H_, lin_b);
}

// round 4
// speedup vs baseline: 1.5484x; 1.5484x over previous
#include <cuda_runtime.h>
#include <math.h>
#include <stdint.h>

#define B_      256
#define L_      16
#define H_      256
#define V_      5000
#define P_      4
#define NPG_    150
#define STEPS_  4
#define OUT_    2000
#define N_      (B_*NPG_)
#define E_      (N_*4)
#define BL_     (B_*L_)
#define LDLOG_  5008

// ---------------- scratch arena ----------------
static constexpr size_t SZ_C    = (size_t)(V_+1)*H_;
static constexpr size_t SZ_XW   = (size_t)BL_*H_;
static constexpr size_t SZ_LOG  = (size_t)BL_*LDLOG_;
static constexpr size_t SZ_VT   = (size_t)BL_*H_;
static constexpr size_t SZ_XG   = (size_t)BL_*4*H_;
static constexpr size_t SZ_G    = (size_t)B_*4*H_;
static constexpr size_t SZ_H    = (size_t)B_*H_;
static constexpr size_t SZ_HINS = (size_t)B_*STEPS_*H_;
static constexpr size_t SZ_TR   = (size_t)N_*3*H_;
static constexpr size_t SZ_ET   = (size_t)E_*H_;

static constexpr size_t OFF_C    = 0;
static constexpr size_t OFF_XW   = OFF_C    + SZ_C;
static constexpr size_t OFF_LOG  = OFF_XW   + SZ_XW;
static constexpr size_t OFF_RM   = OFF_LOG  + SZ_LOG;
static constexpr size_t OFF_RI   = OFF_RM   + BL_;
static constexpr size_t OFF_VT   = OFF_RI   + BL_;
static constexpr size_t OFF_XG   = OFF_VT   + SZ_VT;
static constexpr size_t OFF_G    = OFF_XG   + SZ_XG;
static constexpr size_t OFF_H    = OFF_G    + SZ_G;
static constexpr size_t OFF_CS   = OFF_H    + SZ_H;
static constexpr size_t OFF_HX   = OFF_CS   + SZ_H;
static constexpr size_t OFF_QW   = OFF_HX   + SZ_H;
static constexpr size_t OFF_HINS = OFF_QW   + SZ_H;
static constexpr size_t OFF_R    = OFF_HINS + SZ_HINS;
static constexpr size_t OFF_PS   = OFF_R    + SZ_HINS;
static constexpr size_t OFF_TR   = OFF_PS   + (size_t)B_*P_;
static constexpr size_t OFF_ET   = OFF_TR   + SZ_TR;
static constexpr size_t OFF_NS   = OFF_ET   + SZ_ET;
static constexpr size_t OFF_AGG  = OFF_NS   + N_;
static constexpr size_t OFF_DIST = OFF_AGG  + N_;
static constexpr size_t OFF_CNT  = OFF_DIST + N_;
static constexpr size_t OFF_AGR  = OFF_CNT  + B_;
static constexpr size_t OFF_QA   = OFF_AGR  + SZ_H;
static constexpr size_t OFF_WNT  = OFF_QA   + (size_t)B_*2*H_;
static constexpr size_t OFF_VOCT = OFF_WNT  + (size_t)H_*H_;
static constexpr size_t TOTAL_SCRATCH = OFF_VOCT + (size_t)H_*LDLOG_;

__device__ __align__(16) float g_scratch[TOTAL_SCRATCH];

// ---------------- helpers ----------------
__device__ __forceinline__ float warp_sum(float v) {
    #pragma unroll
    for (int o = 16; o > 0; o >>= 1) v += __shfl_down_sync(0xffffffffu, v, o);
    return v;
}
__device__ __forceinline__ float sigmoidf_(float x) { return 1.f / (1.f + expf(-x)); }
__device__ __forceinline__ uint32_t f2tf32(float x) {
    uint32_t u;
    asm("cvt.rna.tf32.f32 %0, %1;" : "=r"(u) : "f"(x));
    return u;
}
__device__ __forceinline__ void mma_tf32(float* d, const uint32_t* a, const uint32_t* b) {
    asm volatile(
        "mma.sync.aligned.m16n8k8.row.col.f32.tf32.tf32.f32 "
        "{%0,%1,%2,%3}, {%4,%5,%6,%7}, {%8,%9}, {%0,%1,%2,%3};"
        : "+f"(d[0]), "+f"(d[1]), "+f"(d[2]), "+f"(d[3])
        : "r"(a[0]), "r"(a[1]), "r"(a[2]), "r"(a[3]), "r"(b[0]), "r"(b[1]));
}

// ---------------- tensor-core tf32 GEMM (mma.sync) ----------------
// C[m,n] = sum_k A'[m,k]*B[n,k] (+bias[n]); A' = EXPA ? exp(A-rm)*ri : A
// 128x128x32 tiles, 256 thr (8 warps 4x2, warp tile 32x64), dbl-buffered SMEM.
#define TCB_M 128
#define TCB_N 128
#define TCB_K 32
#define TCS   36   // padded K stride (floats)
#define TCBUF (TCB_M*TCS)

template<bool EXPA>
__global__ void __launch_bounds__(256, 1)
mma_gemm_k(const float* __restrict__ A, int lda,
           const float* __restrict__ Bm, int ldb,
           float* __restrict__ C, int ldc,
           int M, int N, int K,
           const float* __restrict__ bias,
           const float* __restrict__ rowmax, const float* __restrict__ rowinv)
{
    extern __shared__ uint32_t sm_[];
    uint32_t* As = sm_;               // 2 * TCBUF
    uint32_t* Bs = sm_ + 2*TCBUF;     // 2 * TCBUF
    const int tid  = threadIdx.x;
    const int wid  = tid >> 5, lane = tid & 31;
    const int g    = lane >> 2, t4 = lane & 3;
    const int wm   = wid & 3, wn = wid >> 2;
    const int bm   = blockIdx.y * TCB_M;
    const int bn   = blockIdx.x * TCB_N;

    float acc[2][8][4];
    #pragma unroll
    for (int i = 0; i < 2; i++)
        #pragma unroll
        for (int j = 0; j < 8; j++)
            #pragma unroll
            for (int q = 0; q < 4; q++) acc[i][j][q] = 0.f;

    float4 pa[4], pb[4];

    // prefetch chunk k0 into regs
    auto ldg_chunk = [&](int k0) {
        #pragma unroll
        for (int i = 0; i < 4; i++) {
            int id = tid + i*256;
            int row = id >> 3, cc = (id & 7) << 2;
            int gm = bm + row, gk = k0 + cc;
            float4 v = make_float4(0.f,0.f,0.f,0.f);
            if (gm < M && gk < K) {           // K,cc multiples of 4 -> full vec valid
                v = *reinterpret_cast<const float4*>(A + (size_t)gm*lda + gk);
                if (EXPA) {
                    float rm_ = rowmax[gm], ri_ = rowinv[gm];
                    v.x = expf(v.x - rm_)*ri_; v.y = expf(v.y - rm_)*ri_;
                    v.z = expf(v.z - rm_)*ri_; v.w = expf(v.w - rm_)*ri_;
                }
            }
            pa[i] = v;
            int gn = bn + row;
            float4 w = make_float4(0.f,0.f,0.f,0.f);
            if (gn < N && gk < K)
                w = *reinterpret_cast<const float4*>(Bm + (size_t)gn*ldb + gk);
            pb[i] = w;
        }
    };
    auto sts_chunk = [&](int buf) {
        uint32_t* a0 = As + buf*TCBUF;
        uint32_t* b0 = Bs + buf*TCBUF;
        #pragma unroll
        for (int i = 0; i < 4; i++) {
            int id = tid + i*256;
            int row = id >> 3, cc = (id & 7) << 2;
            uint32_t* da = a0 + row*TCS + cc;
            da[0] = f2tf32(pa[i].x); da[1] = f2tf32(pa[i].y);
            da[2] = f2tf32(pa[i].z); da[3] = f2tf32(pa[i].w);
            uint32_t* db = b0 + row*TCS + cc;
            db[0] = f2tf32(pb[i].x); db[1] = f2tf32(pb[i].y);
            db[2] = f2tf32(pb[i].z); db[3] = f2tf32(pb[i].w);
        }
    };

    const int nch = (K + TCB_K - 1) / TCB_K;
    ldg_chunk(0);
    sts_chunk(0);
    __syncthreads();

    for (int c = 0; c < nch; c++) {
        if (c + 1 < nch) ldg_chunk((c + 1) * TCB_K);
        const uint32_t* Ab = As + (c & 1)*TCBUF;
        const uint32_t* Bb = Bs + (c & 1)*TCBUF;
        #pragma unroll
        for (int ks = 0; ks < 4; ks++) {
            uint32_t af[2][4], bf[8][2];
            #pragma unroll
            for (int mt = 0; mt < 2; mt++) {
                int r0 = (wm*32 + mt*16 + g)*TCS + ks*8 + t4;
                af[mt][0] = Ab[r0];
                af[mt][1] = Ab[r0 + 8*TCS];
                af[mt][2] = Ab[r0 + 4];
                af[mt][3] = Ab[r0 + 8*TCS + 4];
            }
            #pragma unroll
            for (int nt = 0; nt < 8; nt++) {
                int rb = (wn*64 + nt*8 + g)*TCS + ks*8 + t4;
                bf[nt][0] = Bb[rb];
                bf[nt][1] = Bb[rb + 4];
            }
            #pragma unroll
            for (int mt = 0; mt < 2; mt++)
                #pragma unroll
                for (int nt = 0; nt < 8; nt++)
                    mma_tf32(acc[mt][nt], af[mt], bf[nt]);
        }
        if (c + 1 < nch) {
            sts_chunk((c + 1) & 1);
            __syncthreads();
        }
    }

    // epilogue
    #pragma unroll
    for (int mt = 0; mt < 2; mt++) {
        int row0 = bm + wm*32 + mt*16 + g;
        #pragma unroll
        for (int nt = 0; nt < 8; nt++) {
            int col0 = bn + wn*64 + nt*8 + t4*2;
            float b0v = 0.f, b1v = 0.f;
            if (bias) {
                if (col0     < N) b0v = bias[col0];
                if (col0 + 1 < N) b1v = bias[col0+1];
            }
            if (row0 < M) {
                if (col0     < N) C[(size_t)row0*ldc + col0    ] = acc[mt][nt][0] + b0v;
                if (col0 + 1 < N) C[(size_t)row0*ldc + col0 + 1] = acc[mt][nt][1] + b1v;
            }
            if (row0 + 8 < M) {
                if (col0     < N) C[(size_t)(row0+8)*ldc + col0    ] = acc[mt][nt][2] + b0v;
                if (col0 + 1 < N) C[(size_t)(row0+8)*ldc + col0 + 1] = acc[mt][nt][3] + b1v;
            }
        }
    }
}

#define TC_SMEM_BYTES (4*TCBUF*4)

// ---------------- SIMT fallback GEMM (small/serial) ----------------
template<int BM, int BN, int TM, int TN>
__global__ void __launch_bounds__((BM/TM)*(BN/TN))
gemm_nt_k(const float* __restrict__ A, int lda,
          const float* __restrict__ Bm, int ldb,
          float* __restrict__ C, int ldc,
          int M, int N, int K, const float* __restrict__ bias)
{
    constexpr int BK = 8;
    constexpr int THREADS = (BM/TM)*(BN/TN);
    __shared__ float As[BK][BM];
    __shared__ float Bs[BK][BN];
    const int tid = threadIdx.x;
    const int bm = blockIdx.y * BM;
    const int bn = blockIdx.x * BN;
    const int tx = tid % (BN/TN);
    const int ty = tid / (BN/TN);
    float acc[TM][TN];
    #pragma unroll
    for (int i = 0; i < TM; i++)
        #pragma unroll
        for (int j = 0; j < TN; j++) acc[i][j] = 0.f;

    for (int k0 = 0; k0 < K; k0 += BK) {
        for (int it = tid; it < BM*2; it += THREADS) {
            int m = it >> 1, kq = (it & 1)*4, gm = bm + m;
            float4 v = make_float4(0.f,0.f,0.f,0.f);
            if (gm < M) v = *reinterpret_cast<const float4*>(A + (size_t)gm*lda + k0 + kq);
            As[kq+0][m]=v.x; As[kq+1][m]=v.y; As[kq+2][m]=v.z; As[kq+3][m]=v.w;
        }
        for (int it = tid; it < BN*2; it += THREADS) {
            int n = it >> 1, kq = (it & 1)*4, gn = bn + n;
            float4 v = make_float4(0.f,0.f,0.f,0.f);
            if (gn < N) v = *reinterpret_cast<const float4*>(Bm + (size_t)gn*ldb + k0 + kq);
            Bs[kq+0][n]=v.x; Bs[kq+1][n]=v.y; Bs[kq+2][n]=v.z; Bs[kq+3][n]=v.w;
        }
        __syncthreads();
        #pragma unroll
        for (int k = 0; k < BK; k++) {
            float ar[TM], br[TN];
            #pragma unroll
            for (int i = 0; i < TM; i++) {
                int r = (i < TM/2) ? (ty*(TM/2)+i) : (BM/2 + ty*(TM/2) + (i-TM/2));
                ar[i] = As[k][r];
            }
            #pragma unroll
            for (int j = 0; j < TN; j++) {
                int c = (j < TN/2) ? (tx*(TN/2)+j) : (BN/2 + tx*(TN/2) + (j-TN/2));
                br[j] = Bs[k][c];
            }
            #pragma unroll
            for (int i = 0; i < TM; i++)
                #pragma unroll
                for (int j = 0; j < TN; j++)
                    acc[i][j] = fmaf(ar[i], br[j], acc[i][j]);
        }
        __syncthreads();
    }
    #pragma unroll
    for (int i = 0; i < TM; i++) {
        int r = (i < TM/2) ? (ty*(TM/2)+i) : (BM/2 + ty*(TM/2) + (i-TM/2));
        int gm = bm + r;
        if (gm >= M) continue;
        #pragma unroll
        for (int j = 0; j < TN; j++) {
            int c = (j < TN/2) ? (tx*(TN/2)+j) : (BN/2 + tx*(TN/2) + (j-TN/2));
            int gn = bn + c;
            if (gn >= N) continue;
            float v = acc[i][j];
            if (bias) v += bias[gn];
            C[(size_t)gm*ldc + gn] = v;
        }
    }
}

// ---------------- small kernels ----------------
__global__ void build_c_k(const float* __restrict__ vocab, const float* __restrict__ de,
                          float* __restrict__ Cc) {
    int i = blockIdx.x*256 + threadIdx.x;
    if (i < (V_+1)*H_) Cc[i] = (i < V_*H_) ? vocab[i] : de[i - (size_t)V_*H_];
}

__global__ void transpose_wn_k(const float* __restrict__ W, float* __restrict__ WT) {
    __shared__ float t[32][33];
    int rb = blockIdx.y*32, cb = blockIdx.x*32;
    int x = threadIdx.x, y = threadIdx.y;
    for (int j = y; j < 32; j += 8) t[j][x] = W[(size_t)(rb+j)*H_ + cb + x];
    __syncthreads();
    for (int j = y; j < 32; j += 8) WT[(size_t)(cb+j)*H_ + rb + x] = t[x][j];
}

__global__ void vocab_t_k(const float* __restrict__ vocab, float* __restrict__ vt) {
    __shared__ float t[32][33];
    int vb = blockIdx.x*32, hb = blockIdx.y*32;
    int x = threadIdx.x, y = threadIdx.y;
    for (int j = y; j < 32; j += 8) {
        int v = vb + j;
        t[j][x] = (v < V_) ? vocab[(size_t)v*H_ + hb + x] : 0.f;
    }
    __syncthreads();
    for (int j = y; j < 32; j += 8) {
        int v = vb + x;
        if (v < LDLOG_) vt[(size_t)(hb+j)*LDLOG_ + v] = t[x][j];
    }
}

__global__ void zero_k(float* __restrict__ p, int n) {
    int i = blockIdx.x*256 + threadIdx.x;
    if (i < n) p[i] = 0.f;
}

__global__ void row_softmax_k(const float* __restrict__ Lg, float* __restrict__ rm,
                              float* __restrict__ ri) {
    int r = blockIdx.x;
    const float* row = Lg + (size_t)r*LDLOG_;
    __shared__ float red[256];
    float m = -3.4e38f;
    for (int j = threadIdx.x; j < V_+1; j += 256) m = fmaxf(m, row[j]);
    red[threadIdx.x] = m; __syncthreads();
    for (int o = 128; o > 0; o >>= 1) {
        if (threadIdx.x < o) red[threadIdx.x] = fmaxf(red[threadIdx.x], red[threadIdx.x+o]);
        __syncthreads();
    }
    float M = red[0]; __syncthreads();
    float s = 0.f;
    for (int j = threadIdx.x; j < V_+1; j += 256) s += expf(row[j] - M);
    red[threadIdx.x] = s; __syncthreads();
    for (int o = 128; o > 0; o >>= 1) {
        if (threadIdx.x < o) red[threadIdx.x] += red[threadIdx.x+o];
        __syncthreads();
    }
    if (threadIdx.x == 0) { rm[r] = M; ri[r] = 1.f/red[0]; }
}

__global__ void vtag_eps_k(const float* __restrict__ words, const float* __restrict__ Lg,
                           const float* __restrict__ rm, const float* __restrict__ ri,
                           float* __restrict__ Vt) {
    int i = blockIdx.x*256 + threadIdx.x;
    int r = i >> 8;
    float w = expf(Lg[(size_t)r*LDLOG_ + V_] - rm[r]) * ri[r];
    Vt[i] += w * words[i];
}

__global__ void lstm_gates_k(const float* __restrict__ Xg, const float* __restrict__ Hg,
                             const int* __restrict__ lengths, int t,
                             float* __restrict__ h, float* __restrict__ c) {
    int i = blockIdx.x*256 + threadIdx.x;
    int b = i >> 8, hh = i & 255;
    if (t >= lengths[b]) return;
    const float* xrow = Xg + (size_t)(b*L_ + t)*(4*H_);
    const float* grow = Hg + (size_t)b*(4*H_);
    float gi = xrow[hh]        + grow[hh];
    float gf = xrow[H_ + hh]   + grow[H_ + hh];
    float gc = xrow[2*H_ + hh] + grow[2*H_ + hh];
    float go = xrow[3*H_ + hh] + grow[3*H_ + hh];
    float cn = sigmoidf_(gf)*c[i] + sigmoidf_(gi)*tanhf(gc);
    c[i] = cn;
    h[i] = sigmoidf_(go)*tanhf(cn);
}

__global__ void dec_step_k(const float* __restrict__ Qw, const float* __restrict__ Whh,
                           const float* __restrict__ bhh, int step,
                           float* __restrict__ hx, float* __restrict__ Hins) {
    int b = blockIdx.x, h = threadIdx.x;
    __shared__ float sh[H_];
    sh[h] = hx[b*H_ + h];
    __syncthreads();
    float acc = Qw[b*H_ + h] + bhh[h];
    const float* wr = Whh + (size_t)h*H_;
    #pragma unroll 8
    for (int k = 0; k < H_; k++) acc = fmaf(sh[k], wr[k], acc);
    acc = fmaxf(acc, 0.f);
    hx[b*H_ + h] = acc;
    Hins[((size_t)b*STEPS_ + step)*H_ + h] = acc;
}

__global__ void attention_k(const float* __restrict__ Vt, const float* __restrict__ Hins,
                            const int* __restrict__ lengths, float* __restrict__ R) {
    int b = blockIdx.x, tid = threadIdx.x;
    __shared__ float sV[L_][H_];
    __shared__ float sH[STEPS_][H_];
    __shared__ float satt[STEPS_][L_];
    for (int i = tid; i < L_*H_; i += 256)      sV[i>>8][i&255] = Vt[(size_t)b*L_*H_ + i];
    for (int i = tid; i < STEPS_*H_; i += 256)  sH[i>>8][i&255] = Hins[(size_t)b*STEPS_*H_ + i];
    __syncthreads();
    int warp = tid >> 5, lane = tid & 31;
    for (int pid = warp; pid < STEPS_*L_; pid += 8) {
        int s = pid >> 4, l = pid & 15;
        float a = 0.f;
        #pragma unroll
        for (int q = 0; q < H_/32; q++) a = fmaf(sH[s][lane + 32*q], sV[l][lane + 32*q], a);
        a = warp_sum(a);
        if (lane == 0) satt[s][l] = a;
    }
    __syncthreads();
    if (tid < STEPS_) {
        int len = lengths[b];
        float m = -3.4e38f;
        for (int l = 0; l < len; l++) m = fmaxf(m, satt[tid][l]);
        float s = 0.f;
        for (int l = 0; l < len; l++) { float e = expf(satt[tid][l] - m); satt[tid][l] = e; s += e; }
        float inv = 1.f/s;
        for (int l = 0; l < L_; l++) satt[tid][l] = (l < len) ? satt[tid][l]*inv : 0.f;
    }
    __syncthreads();
    for (int s = 0; s < STEPS_; s++) {
        float acc = 0.f;
        #pragma unroll
        for (int l = 0; l < L_; l++) acc = fmaf(satt[s][l], sV[l][tid], acc);
        R[((size_t)b*STEPS_ + s)*H_ + tid] = acc;
    }
}

__global__ void count_nodes_k(const int* __restrict__ ng, int* __restrict__ cnt) {
    int i = blockIdx.x*256 + threadIdx.x;
    if (i < N_) atomicAdd(&cnt[ng[i]], 1);
}
__global__ void init_dist_k(const int* __restrict__ ng, const int* __restrict__ cnt,
                            float* __restrict__ dist) {
    int i = blockIdx.x*256 + threadIdx.x;
    if (i < N_) dist[i] = 1.f/(float)cnt[ng[i]];
}

__global__ void prop_softmax_k(const float* __restrict__ R, int step,
                               const float* __restrict__ pe, float* __restrict__ ps) {
    int b = blockIdx.x;
    int p = threadIdx.x >> 5, lane = threadIdx.x & 31;
    const float* instr = R + ((size_t)b*STEPS_ + step)*H_;
    float acc = 0.f;
    for (int h = lane; h < H_; h += 32) acc = fmaf(instr[h], pe[p*H_ + h], acc);
    acc = warp_sum(acc);
    __shared__ float s4[P_];
    if (lane == 0) s4[p] = acc;
    __syncthreads();
    if (threadIdx.x == 0) {
        float m = fmaxf(fmaxf(s4[0], s4[1]), fmaxf(s4[2], s4[3]));
        float e0 = expf(s4[0]-m), e1 = expf(s4[1]-m), e2 = expf(s4[2]-m), e3 = expf(s4[3]-m);
        float inv = 1.f/(e0+e1+e2+e3);
        ps[b*P_+0] = e0*inv; ps[b*P_+1] = e1*inv; ps[b*P_+2] = e2*inv; ps[b*P_+3] = e3*inv;
    }
}

__global__ void node_pass_k(const float* __restrict__ Tr, const float* __restrict__ R, int step,
                            const float* __restrict__ ps, const float* __restrict__ Wst,
                            const int* __restrict__ ng, float* __restrict__ nst) {
    int n = (blockIdx.x*blockDim.x + threadIdx.x) >> 5;
    int lane = threadIdx.x & 31;
    if (n >= N_) return;
    int g = ng[n];
    const float* instr = R + ((size_t)g*STEPS_ + step)*H_;
    float p0 = ps[g*P_+0], p1 = ps[g*P_+1], p2 = ps[g*P_+2];
    const float* T = Tr + (size_t)n*3*H_;
    float acc = 0.f;
    #pragma unroll
    for (int q = 0; q < H_/32; q++) {
        int h = lane + 32*q;
        float tv = p0*T[h] + p1*T[H_+h] + p2*T[2*H_+h];
        float x = instr[h]*tv;
        float e = (x > 0.f) ? x : expm1f(x);
        acc = fmaf(e, Wst[h], acc);
    }
    acc = warp_sum(acc);
    if (lane == 0) nst[n] = acc;
}

__global__ void edge_pass_k(const float* __restrict__ Et, const float* __restrict__ R, int step,
                            const float* __restrict__ Wrel,
                            const int* __restrict__ eg, const int* __restrict__ esrc,
                            const int* __restrict__ edst,
                            const float* __restrict__ dist, float* __restrict__ agg) {
    int e = (blockIdx.x*blockDim.x + threadIdx.x) >> 5;
    int lane = threadIdx.x & 31;
    if (e >= E_) return;
    int g = eg[e];
    const float* instr = R + ((size_t)g*STEPS_ + step)*H_;
    const float* et = Et + (size_t)e*H_;
    float acc = 0.f;
    #pragma unroll
    for (int q = 0; q < H_/32; q++) {
        int h = lane + 32*q;
        float x = instr[h]*et[h];
        float el = (x > 0.f) ? x : expm1f(x);
        acc = fmaf(el, Wrel[h], acc);
    }
    acc = warp_sum(acc);
    if (lane == 0) atomicAdd(&agg[edst[e]], dist[esrc[e]]*acc);
}

__global__ void seg_update_k(const float* __restrict__ nst, const float* __restrict__ agg,
                             const float* __restrict__ ps, float* __restrict__ dist) {
    int g = blockIdx.x, tid = threadIdx.x;
    __shared__ float red[256];
    float v1 = (tid < NPG_) ? nst[g*NPG_ + tid] : -3.4e38f;
    float v2 = (tid < NPG_) ? agg[g*NPG_ + tid] : -3.4e38f;
    red[tid] = v1; __syncthreads();
    for (int o = 128; o > 0; o >>= 1) { if (tid < o) red[tid] = fmaxf(red[tid], red[tid+o]); __syncthreads(); }
    float m1 = red[0]; __syncthreads();
    red[tid] = v2; __syncthreads();
    for (int o = 128; o > 0; o >>= 1) { if (tid < o) red[tid] = fmaxf(red[tid], red[tid+o]); __syncthreads(); }
    float m2 = red[0]; __syncthreads();
    float e1 = (tid < NPG_) ? expf(v1 - m1) : 0.f;
    float e2 = (tid < NPG_) ? expf(v2 - m2) : 0.f;
    red[tid] = e1; __syncthreads();
    for (int o = 128; o > 0; o >>= 1) { if (tid < o) red[tid] += red[tid+o]; __syncthreads(); }
    float s1 = red[0]; __syncthreads();
    red[tid] = e2; __syncthreads();
    for (int o = 128; o > 0; o >>= 1) { if (tid < o) red[tid] += red[tid+o]; __syncthreads(); }
    float s2 = red[0];
    if (tid < NPG_) {
        float r = ps[g*P_ + 3];
        dist[g*NPG_ + tid] = r*(e2/s2) + (1.f - r)*(e1/s1);
    }
}

__global__ void final_agg_k(const float* __restrict__ na, const float* __restrict__ ps,
                            const float* __restrict__ dist, float* __restrict__ agr) {
    int g = blockIdx.x, h = threadIdx.x;
    float p0 = ps[g*P_], p1 = ps[g*P_+1], p2 = ps[g*P_+2];
    float acc = 0.f;
    for (int i = 0; i < NPG_; i++) {
        size_t n = (size_t)g*NPG_ + i;
        const float* a = na + n*3*H_;
        float nf = p0*a[h] + p1*a[H_+h] + p2*a[2*H_+h];
        acc = fmaf(dist[n], nf, acc);
    }
    agr[g*H_ + h] = acc;
}

__global__ void build_qa_k(const float* __restrict__ Q, const float* __restrict__ agr,
                           float* __restrict__ QA) {
    int i = blockIdx.x*256 + threadIdx.x;
    int b = i >> 9, k = i & 511;
    QA[i] = (k < H_) ? Q[b*H_ + k] : agr[b*H_ + (k - H_)];
}

// ---------------- launchers ----------------
static inline void tc_gemm(const float* A, int lda, const float* Bm, int ldb,
                           float* C, int ldc, int M, int N, int K, const float* bias) {
    dim3 g((N + TCB_N - 1)/TCB_N, (M + TCB_M - 1)/TCB_M);
    mma_gemm_k<false><<<g, 256, TC_SMEM_BYTES>>>(A, lda, Bm, ldb, C, ldc, M, N, K,
                                                 bias, nullptr, nullptr);
}
static inline void tc_gemm_expa(const float* A, int lda, const float* Bm, int ldb,
                                float* C, int ldc, int M, int N, int K,
                                const float* rm, const float* ri) {
    dim3 g((N + TCB_N - 1)/TCB_N, (M + TCB_M - 1)/TCB_M);
    mma_gemm_k<true><<<g, 256, TC_SMEM_BYTES>>>(A, lda, Bm, ldb, C, ldc, M, N, K,
                                                nullptr, rm, ri);
}
static inline void gemm64_nt(const float* A, int lda, const float* Bm, int ldb,
                             float* C, int ldc, int M, int N, int K, const float* bias) {
    dim3 g((N + 63)/64, (M + 63)/64);
    gemm_nt_k<64,64,4,4><<<g, 256>>>(A, lda, Bm, ldb, C, ldc, M, N, K, bias);
}

extern "C" void kernel_launch(void* const* d_in, const int* in_sizes, int n_in,
                              void* d_out, int out_size) {
    const float* questions     = (const float*)d_in[0];
    const float* node_attrs    = (const float*)d_in[1];
    const float* edge_attrs    = (const float*)d_in[2];
    const float* vocab         = (const float*)d_in[3];
    const float* default_embed = (const float*)d_in[4];
    const float* W_norm        = (const float*)d_in[5];
    const float* lstm_Wih      = (const float*)d_in[6];
    const float* lstm_Whh      = (const float*)d_in[7];
    const float* lstm_bih      = (const float*)d_in[8];
    const float* lstm_bhh      = (const float*)d_in[9];
    const float* rnn_Wih       = (const float*)d_in[10];
    const float* rnn_Whh       = (const float*)d_in[11];
    const float* rnn_bih       = (const float*)d_in[12];
    const float* rnn_bhh       = (const float*)d_in[13];
    const float* prop_embeds   = (const float*)d_in[14];
    const float* Ws_property   = (const float*)d_in[15];
    const float* W_state       = (const float*)d_in[16];
    const float* W_relation    = (const float*)d_in[17];
    const float* lin_W         = (const float*)d_in[18];
    const float* lin_b         = (const float*)d_in[19];
    const int*   lengths       = (const int*)d_in[20];
    const int*   node_graph    = (const int*)d_in[21];
    const int*   edge_graph    = (const int*)d_in[22];
    const int*   edge_src      = (const int*)d_in[23];
    const int*   edge_dst      = (const int*)d_in[24];
    float* out = (float*)d_out;

    cudaFuncSetAttribute(mma_gemm_k<false>, cudaFuncAttributeMaxDynamicSharedMemorySize, TC_SMEM_BYTES);
    cudaFuncSetAttribute(mma_gemm_k<true>,  cudaFuncAttributeMaxDynamicSharedMemorySize, TC_SMEM_BYTES);

    float* S = nullptr;
    cudaGetSymbolAddress((void**)&S, g_scratch);
    float* Cc   = S + OFF_C;
    float* XW   = S + OFF_XW;
    float* LG   = S + OFF_LOG;
    float* RM   = S + OFF_RM;
    float* RI   = S + OFF_RI;
    float* VT   = S + OFF_VT;
    float* XG   = S + OFF_XG;
    float* G    = S + OFF_G;
    float* Hh   = S + OFF_H;
    float* HX   = S + OFF_HX;
    float* QW   = S + OFF_QW;
    float* HINS = S + OFF_HINS;
    float* Rr   = S + OFF_R;
    float* PS   = S + OFF_PS;
    float* TR   = S + OFF_TR;
    float* ET   = S + OFF_ET;
    float* NS   = S + OFF_NS;
    float* AGG  = S + OFF_AGG;
    float* DIST = S + OFF_DIST;
    int*   CNT  = (int*)(S + OFF_CNT);
    float* AGR  = S + OFF_AGR;
    float* QA   = S + OFF_QA;
    float* WNT  = S + OFF_WNT;
    float* VOCT = S + OFF_VOCT;

    // 0. one-time layout prep
    build_c_k<<<((V_+1)*H_ + 255)/256, 256>>>(vocab, default_embed, Cc);
    transpose_wn_k<<<dim3(8,8), dim3(32,8)>>>(W_norm, WNT);
    vocab_t_k<<<dim3((LDLOG_+31)/32, H_/32), dim3(32,8)>>>(vocab, VOCT);

    // 1. vocab tagging (tensor cores)
    tc_gemm(questions, H_, WNT, H_, XW, H_, BL_, H_, H_, nullptr);
    tc_gemm(XW, H_, Cc, H_, LG, LDLOG_, BL_, V_+1, H_, nullptr);
    row_softmax_k<<<BL_, 256>>>(LG, RM, RI);
    tc_gemm_expa(LG, LDLOG_, VOCT, LDLOG_, VT, H_, BL_, H_, V_, RM, RI);
    vtag_eps_k<<<BL_*H_/256, 256>>>(questions, LG, RM, RI, VT);

    // 2. LSTM encoder
    tc_gemm(VT, H_, lstm_Wih, H_, XG, 4*H_, BL_, 4*H_, H_, lstm_bih);
    zero_k<<<(2*B_*H_ + 255)/256, 256>>>(Hh, 2*B_*H_);
    for (int t = 0; t < L_; t++) {
        gemm64_nt(Hh, H_, lstm_Whh, H_, G, 4*H_, B_, 4*H_, H_, lstm_bhh);
        lstm_gates_k<<<B_*H_/256, 256>>>(XG, G, lengths, t, Hh, S + OFF_CS);
    }

    // 3. decoder RNN + attention
    gemm64_nt(Hh, H_, rnn_Wih, H_, QW, H_, B_, H_, H_, rnn_bih);
    zero_k<<<(B_*H_ + 255)/256, 256>>>(HX, B_*H_);
    for (int s = 0; s < STEPS_; s++)
        dec_step_k<<<B_, H_>>>(QW, rnn_Whh, rnn_bhh, s, HX, HINS);
    attention_k<<<B_, 256>>>(VT, HINS, lengths, Rr);

    // 4. loop-invariant graph transforms (tensor cores)
    for (int p = 0; p < 3; p++)
        tc_gemm(node_attrs + p*H_, 3*H_, Ws_property + (size_t)p*H_*H_, H_,
                TR + p*H_, 3*H_, N_, H_, H_, nullptr);
    tc_gemm(edge_attrs, H_, Ws_property + (size_t)3*H_*H_, H_, ET, H_, E_, H_, H_, nullptr);

    zero_k<<<1, 256>>>((float*)CNT, B_);
    count_nodes_k<<<(N_ + 255)/256, 256>>>(node_graph, CNT);
    init_dist_k<<<(N_ + 255)/256, 256>>>(node_graph, CNT, DIST);

    // 5. 4 reasoning steps
    for (int s = 0; s < STEPS_; s++) {
        prop_softmax_k<<<B_, 128>>>(Rr, s, prop_embeds, PS);
        node_pass_k<<<N_*32/256, 256>>>(TR, Rr, s, PS, W_state, node_graph, NS);
        zero_k<<<(N_ + 255)/256, 256>>>(AGG, N_);
        edge_pass_k<<<E_*32/256, 256>>>(ET, Rr, s, W_relation, edge_graph, edge_src, edge_dst, DIST, AGG);
        seg_update_k<<<B_, 256>>>(NS, AGG, PS, DIST);
    }

    // 6. final aggregation + output projection
    final_agg_k<<<B_, 256>>>(node_attrs, PS, DIST, AGR);
    build_qa_k<<<B_*2*H_/256, 256>>>(Hh, AGR, QA);
    tc_gemm(QA, 2*H_, lin_W, 2*H_, out, OUT_, B_, OUT_, 2*H_, lin_b);
}

// round 5
// speedup vs baseline: 1.7647x; 1.1397x over previous
#include <cuda_runtime.h>
#include <math.h>
#include <stdint.h>

#define B_      256
#define L_      16
#define H_      256
#define V_      5000
#define P_      4
#define NPG_    150
#define STEPS_  4
#define OUT_    2000
#define N_      (B_*NPG_)
#define E_      (N_*4)
#define BL_     (B_*L_)
#define LDLOG_  5008

// ---------------- scratch arena ----------------
static constexpr size_t SZ_C    = (size_t)(V_+1)*H_;
static constexpr size_t SZ_XW   = (size_t)BL_*H_;
static constexpr size_t SZ_LOG  = (size_t)BL_*LDLOG_;
static constexpr size_t SZ_VT   = (size_t)BL_*H_;
static constexpr size_t SZ_XG   = (size_t)BL_*4*H_;
static constexpr size_t SZ_G    = (size_t)B_*4*H_;
static constexpr size_t SZ_H    = (size_t)B_*H_;
static constexpr size_t SZ_HINS = (size_t)B_*STEPS_*H_;
static constexpr size_t SZ_TR   = (size_t)N_*3*H_;
static constexpr size_t SZ_ET   = (size_t)E_*H_;

static constexpr size_t OFF_C    = 0;
static constexpr size_t OFF_XW   = OFF_C    + SZ_C;
static constexpr size_t OFF_LOG  = OFF_XW   + SZ_XW;
static constexpr size_t OFF_RM   = OFF_LOG  + SZ_LOG;
static constexpr size_t OFF_RI   = OFF_RM   + BL_;
static constexpr size_t OFF_VT   = OFF_RI   + BL_;
static constexpr size_t OFF_XG   = OFF_VT   + SZ_VT;
static constexpr size_t OFF_G    = OFF_XG   + SZ_XG;
static constexpr size_t OFF_H    = OFF_G    + SZ_G;
static constexpr size_t OFF_CS   = OFF_H    + SZ_H;
static constexpr size_t OFF_HX   = OFF_CS   + SZ_H;
static constexpr size_t OFF_QW   = OFF_HX   + SZ_H;
static constexpr size_t OFF_HINS = OFF_QW   + SZ_H;
static constexpr size_t OFF_R    = OFF_HINS + SZ_HINS;
static constexpr size_t OFF_PS   = OFF_R    + SZ_HINS;
static constexpr size_t OFF_TR   = OFF_PS   + (size_t)B_*P_;
static constexpr size_t OFF_ET   = OFF_TR   + SZ_TR;
static constexpr size_t OFF_NS   = OFF_ET   + SZ_ET;
static constexpr size_t OFF_AGG  = OFF_NS   + N_;
static constexpr size_t OFF_DIST = OFF_AGG  + N_;
static constexpr size_t OFF_CNT  = OFF_DIST + N_;
static constexpr size_t OFF_AGR  = OFF_CNT  + B_;
static constexpr size_t OFF_QA   = OFF_AGR  + SZ_H;
static constexpr size_t OFF_WNT  = OFF_QA   + (size_t)B_*2*H_;
static constexpr size_t OFF_VOCT = OFF_WNT  + (size_t)H_*H_;
static constexpr size_t TOTAL_SCRATCH = OFF_VOCT + (size_t)H_*LDLOG_;

__device__ __align__(16) float g_scratch[TOTAL_SCRATCH];

// ---------------- helpers ----------------
__device__ __forceinline__ float warp_sum(float v) {
    #pragma unroll
    for (int o = 16; o > 0; o >>= 1) v += __shfl_down_sync(0xffffffffu, v, o);
    return v;
}
__device__ __forceinline__ float sigmoidf_(float x) { return 1.f / (1.f + expf(-x)); }
__device__ __forceinline__ uint32_t f2tf32(float x) {
    uint32_t u;
    asm("cvt.rna.tf32.f32 %0, %1;" : "=r"(u) : "f"(x));
    return u;
}
__device__ __forceinline__ uint32_t smem_u32(const void* p) {
    uint32_t a;
    asm("{ .reg .u64 t; cvta.to.shared.u64 t, %1; cvt.u32.u64 %0, t; }" : "=r"(a) : "l"(p));
    return a;
}
__device__ __forceinline__ void cp_async16(void* sdst, const void* gsrc, bool pred) {
    uint32_t d = smem_u32(sdst);
    int sz = pred ? 16 : 0;
    asm volatile("cp.async.cg.shared.global [%0], [%1], 16, %2;"
                 :: "r"(d), "l"(gsrc), "r"(sz));
}
__device__ __forceinline__ void cp_commit() {
    asm volatile("cp.async.commit_group;" ::: "memory");
}
template<int N>
__device__ __forceinline__ void cp_wait() {
    asm volatile("cp.async.wait_group %0;" :: "n"(N) : "memory");
}
__device__ __forceinline__ void mma_tf32(float* d, const uint32_t* a, const uint32_t* b) {
    asm volatile(
        "mma.sync.aligned.m16n8k8.row.col.f32.tf32.tf32.f32 "
        "{%0,%1,%2,%3}, {%4,%5,%6,%7}, {%8,%9}, {%0,%1,%2,%3};"
        : "+f"(d[0]), "+f"(d[1]), "+f"(d[2]), "+f"(d[3])
        : "r"(a[0]), "r"(a[1]), "r"(a[2]), "r"(a[3]), "r"(b[0]), "r"(b[1]));
}

// ---------------- tensor-core tf32 GEMM (mma.sync + cp.async) ----------------
// C[m,n] = sum_k A'[m,k]*B[n,k] (+bias[n]); A' = EXPA ? exp(A-rm)*ri : A
// 128x64x32 tiles, 256 thr (8 warps 4x2, warp tile 32x32), dbl-buffer cp.async.
#define TCB_M 128
#define TCB_N 64
#define TCB_K 32
#define TAS   36
#define ABUF  (TCB_M*TAS)
#define BBUF  (TCB_N*TAS)
#define TC_SMEM_BYTES ((2*ABUF + 2*BBUF)*4)

template<bool EXPA>
__global__ void __launch_bounds__(256, 2)
mma_gemm_k(const float* __restrict__ A, int lda,
           const float* __restrict__ Bm, int ldb,
           float* __restrict__ C, int ldc,
           int M, int N, int K,
           const float* __restrict__ bias,
           const float* __restrict__ rowmax, const float* __restrict__ rowinv)
{
    extern __shared__ float smf[];
    float* As = smf;                 // 2 * ABUF
    float* Bs = smf + 2*ABUF;        // 2 * BBUF
    const int tid  = threadIdx.x;
    const int wid  = tid >> 5, lane = tid & 31;
    const int g    = lane >> 2, t4 = lane & 3;
    const int wm   = wid & 3, wn = wid >> 2;
    const int bm   = blockIdx.y * TCB_M;
    const int bn   = blockIdx.x * TCB_N;

    float acc[2][4][4];
    #pragma unroll
    for (int i = 0; i < 2; i++)
        #pragma unroll
        for (int j = 0; j < 4; j++)
            #pragma unroll
            for (int q = 0; q < 4; q++) acc[i][j][q] = 0.f;

    const int arow = tid >> 3, acc4 = (tid & 7) << 2;   // A: 4 rounds of 256 thr
    const int brow = tid >> 3;                          // B: 2 rounds

    float4 pa[4];   // EXPA register-staged A

    auto issue_chunk = [&](int c) {
        int k0 = c * TCB_K;
        int buf = c & 1;
        if (!EXPA) {
            #pragma unroll
            for (int i = 0; i < 4; i++) {
                int row = arow + i*32;
                int gm = bm + row, gk = k0 + acc4;
                cp_async16(As + buf*ABUF + row*TAS + acc4,
                           A + (size_t)gm*lda + gk, (gm < M) && (gk < K));
            }
        }
        #pragma unroll
        for (int i = 0; i < 2; i++) {
            int row = brow + i*32;
            int gn = bn + row, gk = k0 + acc4;
            cp_async16(Bs + buf*BBUF + row*TAS + acc4,
                       Bm + (size_t)gn*ldb + gk, (gn < N) && (gk < K));
        }
        cp_commit();
    };
    auto ldg_a_exp = [&](int c) {
        int k0 = c * TCB_K;
        #pragma unroll
        for (int i = 0; i < 4; i++) {
            int row = arow + i*32;
            int gm = bm + row, gk = k0 + acc4;
            float4 v = make_float4(-1e30f, -1e30f, -1e30f, -1e30f);
            if (gm < M && gk < K)
                v = *reinterpret_cast<const float4*>(A + (size_t)gm*lda + gk);
            if (gm < M) {
                float rm_ = rowmax[gm], ri_ = rowinv[gm];
                v.x = expf(v.x - rm_)*ri_; v.y = expf(v.y - rm_)*ri_;
                v.z = expf(v.z - rm_)*ri_; v.w = expf(v.w - rm_)*ri_;
            }
            pa[i] = v;
        }
    };
    auto sts_a_exp = [&](int c) {
        int buf = c & 1;
        #pragma unroll
        for (int i = 0; i < 4; i++) {
            int row = arow + i*32;
            float* d = As + buf*ABUF + row*TAS + acc4;
            d[0] = pa[i].x; d[1] = pa[i].y; d[2] = pa[i].z; d[3] = pa[i].w;
        }
    };

    const int nch = (K + TCB_K - 1) / TCB_K;
    if (EXPA) { ldg_a_exp(0); sts_a_exp(0); }
    issue_chunk(0);

    for (int c = 0; c < nch; c++) {
        if (c + 1 < nch) {
            if (EXPA) { ldg_a_exp(c + 1); sts_a_exp(c + 1); }
            issue_chunk(c + 1);
            cp_wait<1>();
        } else {
            cp_wait<0>();
        }
        __syncthreads();

        const float* Ab = As + (c & 1)*ABUF;
        const float* Bb = Bs + (c & 1)*BBUF;
        #pragma unroll
        for (int ks = 0; ks < 4; ks++) {
            uint32_t af[2][4], bf[4][2];
            #pragma unroll
            for (int mt = 0; mt < 2; mt++) {
                int r0 = (wm*32 + mt*16 + g)*TAS + ks*8 + t4;
                af[mt][0] = f2tf32(Ab[r0]);
                af[mt][1] = f2tf32(Ab[r0 + 8*TAS]);
                af[mt][2] = f2tf32(Ab[r0 + 4]);
                af[mt][3] = f2tf32(Ab[r0 + 8*TAS + 4]);
            }
            #pragma unroll
            for (int nt = 0; nt < 4; nt++) {
                int rb = (wn*32 + nt*8 + g)*TAS + ks*8 + t4;
                bf[nt][0] = f2tf32(Bb[rb]);
                bf[nt][1] = f2tf32(Bb[rb + 4]);
            }
            #pragma unroll
            for (int mt = 0; mt < 2; mt++)
                #pragma unroll
                for (int nt = 0; nt < 4; nt++)
                    mma_tf32(acc[mt][nt], af[mt], bf[nt]);
        }
        __syncthreads();
    }

    // epilogue
    #pragma unroll
    for (int mt = 0; mt < 2; mt++) {
        int row0 = bm + wm*32 + mt*16 + g;
        #pragma unroll
        for (int nt = 0; nt < 4; nt++) {
            int col0 = bn + wn*32 + nt*8 + t4*2;
            float b0v = 0.f, b1v = 0.f;
            if (bias) {
                if (col0     < N) b0v = bias[col0];
                if (col0 + 1 < N) b1v = bias[col0+1];
            }
            if (row0 < M) {
                if (col0     < N) C[(size_t)row0*ldc + col0    ] = acc[mt][nt][0] + b0v;
                if (col0 + 1 < N) C[(size_t)row0*ldc + col0 + 1] = acc[mt][nt][1] + b1v;
            }
            if (row0 + 8 < M) {
                if (col0     < N) C[(size_t)(row0+8)*ldc + col0    ] = acc[mt][nt][2] + b0v;
                if (col0 + 1 < N) C[(size_t)(row0+8)*ldc + col0 + 1] = acc[mt][nt][3] + b1v;
            }
        }
    }
}

// ---------------- SIMT fallback GEMM (LSTM/decoder fp32 path) ----------------
template<int BM, int BN, int TM, int TN>
__global__ void __launch_bounds__((BM/TM)*(BN/TN))
gemm_nt_k(const float* __restrict__ A, int lda,
          const float* __restrict__ Bm, int ldb,
          float* __restrict__ C, int ldc,
          int M, int N, int K, const float* __restrict__ bias)
{
    constexpr int BK = 8;
    constexpr int THREADS = (BM/TM)*(BN/TN);
    __shared__ float As[BK][BM];
    __shared__ float Bs[BK][BN];
    const int tid = threadIdx.x;
    const int bm = blockIdx.y * BM;
    const int bn = blockIdx.x * BN;
    const int tx = tid % (BN/TN);
    const int ty = tid / (BN/TN);
    float acc[TM][TN];
    #pragma unroll
    for (int i = 0; i < TM; i++)
        #pragma unroll
        for (int j = 0; j < TN; j++) acc[i][j] = 0.f;

    for (int k0 = 0; k0 < K; k0 += BK) {
        for (int it = tid; it < BM*2; it += THREADS) {
            int m = it >> 1, kq = (it & 1)*4, gm = bm + m;
            float4 v = make_float4(0.f,0.f,0.f,0.f);
            if (gm < M) v = *reinterpret_cast<const float4*>(A + (size_t)gm*lda + k0 + kq);
            As[kq+0][m]=v.x; As[kq+1][m]=v.y; As[kq+2][m]=v.z; As[kq+3][m]=v.w;
        }
        for (int it = tid; it < BN*2; it += THREADS) {
            int n = it >> 1, kq = (it & 1)*4, gn = bn + n;
            float4 v = make_float4(0.f,0.f,0.f,0.f);
            if (gn < N) v = *reinterpret_cast<const float4*>(Bm + (size_t)gn*ldb + k0 + kq);
            Bs[kq+0][n]=v.x; Bs[kq+1][n]=v.y; Bs[kq+2][n]=v.z; Bs[kq+3][n]=v.w;
        }
        __syncthreads();
        #pragma unroll
        for (int k = 0; k < BK; k++) {
            float ar[TM], br[TN];
            #pragma unroll
            for (int i = 0; i < TM; i++) {
                int r = (i < TM/2) ? (ty*(TM/2)+i) : (BM/2 + ty*(TM/2) + (i-TM/2));
                ar[i] = As[k][r];
            }
            #pragma unroll
            for (int j = 0; j < TN; j++) {
                int c = (j < TN/2) ? (tx*(TN/2)+j) : (BN/2 + tx*(TN/2) + (j-TN/2));
                br[j] = Bs[k][c];
            }
            #pragma unroll
            for (int i = 0; i < TM; i++)
                #pragma unroll
                for (int j = 0; j < TN; j++)
                    acc[i][j] = fmaf(ar[i], br[j], acc[i][j]);
        }
        __syncthreads();
    }
    #pragma unroll
    for (int i = 0; i < TM; i++) {
        int r = (i < TM/2) ? (ty*(TM/2)+i) : (BM/2 + ty*(TM/2) + (i-TM/2));
        int gm = bm + r;
        if (gm >= M) continue;
        #pragma unroll
        for (int j = 0; j < TN; j++) {
            int c = (j < TN/2) ? (tx*(TN/2)+j) : (BN/2 + tx*(TN/2) + (j-TN/2));
            int gn = bn + c;
            if (gn >= N) continue;
            float v = acc[i][j];
            if (bias) v += bias[gn];
            C[(size_t)gm*ldc + gn] = v;
        }
    }
}

// ---------------- small kernels ----------------
__global__ void build_c_k(const float* __restrict__ vocab, const float* __restrict__ de,
                          float* __restrict__ Cc) {
    int i = blockIdx.x*256 + threadIdx.x;
    if (i < (V_+1)*H_) Cc[i] = (i < V_*H_) ? vocab[i] : de[i - (size_t)V_*H_];
}

__global__ void transpose_wn_k(const float* __restrict__ W, float* __restrict__ WT) {
    __shared__ float t[32][33];
    int rb = blockIdx.y*32, cb = blockIdx.x*32;
    int x = threadIdx.x, y = threadIdx.y;
    for (int j = y; j < 32; j += 8) t[j][x] = W[(size_t)(rb+j)*H_ + cb + x];
    __syncthreads();
    for (int j = y; j < 32; j += 8) WT[(size_t)(cb+j)*H_ + rb + x] = t[x][j];
}

__global__ void vocab_t_k(const float* __restrict__ vocab, float* __restrict__ vt) {
    __shared__ float t[32][33];
    int vb = blockIdx.x*32, hb = blockIdx.y*32;
    int x = threadIdx.x, y = threadIdx.y;
    for (int j = y; j < 32; j += 8) {
        int v = vb + j;
        t[j][x] = (v < V_) ? vocab[(size_t)v*H_ + hb + x] : 0.f;
    }
    __syncthreads();
    for (int j = y; j < 32; j += 8) {
        int v = vb + x;
        if (v < LDLOG_) vt[(size_t)(hb+j)*LDLOG_ + v] = t[x][j];
    }
}

__global__ void zero_k(float* __restrict__ p, int n) {
    int i = blockIdx.x*256 + threadIdx.x;
    if (i < n) p[i] = 0.f;
}

__global__ void row_softmax_k(const float* __restrict__ Lg, float* __restrict__ rm,
                              float* __restrict__ ri) {
    int r = blockIdx.x;
    const float* row = Lg + (size_t)r*LDLOG_;
    __shared__ float red[256];
    float m = -3.4e38f;
    for (int j = threadIdx.x; j < V_+1; j += 256) m = fmaxf(m, row[j]);
    red[threadIdx.x] = m; __syncthreads();
    for (int o = 128; o > 0; o >>= 1) {
        if (threadIdx.x < o) red[threadIdx.x] = fmaxf(red[threadIdx.x], red[threadIdx.x+o]);
        __syncthreads();
    }
    float M = red[0]; __syncthreads();
    float s = 0.f;
    for (int j = threadIdx.x; j < V_+1; j += 256) s += expf(row[j] - M);
    red[threadIdx.x] = s; __syncthreads();
    for (int o = 128; o > 0; o >>= 1) {
        if (threadIdx.x < o) red[threadIdx.x] += red[threadIdx.x+o];
        __syncthreads();
    }
    if (threadIdx.x == 0) { rm[r] = M; ri[r] = 1.f/red[0]; }
}

__global__ void vtag_eps_k(const float* __restrict__ words, const float* __restrict__ Lg,
                           const float* __restrict__ rm, const float* __restrict__ ri,
                           float* __restrict__ Vt) {
    int i = blockIdx.x*256 + threadIdx.x;
    int r = i >> 8;
    float w = expf(Lg[(size_t)r*LDLOG_ + V_] - rm[r]) * ri[r];
    Vt[i] += w * words[i];
}

__global__ void lstm_gates_k(const float* __restrict__ Xg, const float* __restrict__ Hg,
                             const int* __restrict__ lengths, int t,
                             float* __restrict__ h, float* __restrict__ c) {
    int i = blockIdx.x*256 + threadIdx.x;
    int b = i >> 8, hh = i & 255;
    if (t >= lengths[b]) return;
    const float* xrow = Xg + (size_t)(b*L_ + t)*(4*H_);
    const float* grow = Hg + (size_t)b*(4*H_);
    float gi = xrow[hh]        + grow[hh];
    float gf = xrow[H_ + hh]   + grow[H_ + hh];
    float gc = xrow[2*H_ + hh] + grow[2*H_ + hh];
    float go = xrow[3*H_ + hh] + grow[3*H_ + hh];
    float cn = sigmoidf_(gf)*c[i] + sigmoidf_(gi)*tanhf(gc);
    c[i] = cn;
    h[i] = sigmoidf_(go)*tanhf(cn);
}

__global__ void dec_step_k(const float* __restrict__ Qw, const float* __restrict__ Whh,
                           const float* __restrict__ bhh, int step,
                           float* __restrict__ hx, float* __restrict__ Hins) {
    int b = blockIdx.x, h = threadIdx.x;
    __shared__ float sh[H_];
    sh[h] = hx[b*H_ + h];
    __syncthreads();
    float acc = Qw[b*H_ + h] + bhh[h];
    const float* wr = Whh + (size_t)h*H_;
    #pragma unroll 8
    for (int k = 0; k < H_; k++) acc = fmaf(sh[k], wr[k], acc);
    acc = fmaxf(acc, 0.f);
    hx[b*H_ + h] = acc;
    Hins[((size_t)b*STEPS_ + step)*H_ + h] = acc;
}

__global__ void attention_k(const float* __restrict__ Vt, const float* __restrict__ Hins,
                            const int* __restrict__ lengths, float* __restrict__ R) {
    int b = blockIdx.x, tid = threadIdx.x;
    __shared__ float sV[L_][H_];
    __shared__ float sH[STEPS_][H_];
    __shared__ float satt[STEPS_][L_];
    for (int i = tid; i < L_*H_; i += 256)      sV[i>>8][i&255] = Vt[(size_t)b*L_*H_ + i];
    for (int i = tid; i < STEPS_*H_; i += 256)  sH[i>>8][i&255] = Hins[(size_t)b*STEPS_*H_ + i];
    __syncthreads();
    int warp = tid >> 5, lane = tid & 31;
    for (int pid = warp; pid < STEPS_*L_; pid += 8) {
        int s = pid >> 4, l = pid & 15;
        float a = 0.f;
        #pragma unroll
        for (int q = 0; q < H_/32; q++) a = fmaf(sH[s][lane + 32*q], sV[l][lane + 32*q], a);
        a = warp_sum(a);
        if (lane == 0) satt[s][l] = a;
    }
    __syncthreads();
    if (tid < STEPS_) {
        int len = lengths[b];
        float m = -3.4e38f;
        for (int l = 0; l < len; l++) m = fmaxf(m, satt[tid][l]);
        float s = 0.f;
        for (int l = 0; l < len; l++) { float e = expf(satt[tid][l] - m); satt[tid][l] = e; s += e; }
        float inv = 1.f/s;
        for (int l = 0; l < L_; l++) satt[tid][l] = (l < len) ? satt[tid][l]*inv : 0.f;
    }
    __syncthreads();
    for (int s = 0; s < STEPS_; s++) {
        float acc = 0.f;
        #pragma unroll
        for (int l = 0; l < L_; l++) acc = fmaf(satt[s][l], sV[l][tid], acc);
        R[((size_t)b*STEPS_ + s)*H_ + tid] = acc;
    }
}

__global__ void count_nodes_k(const int* __restrict__ ng, int* __restrict__ cnt) {
    int i = blockIdx.x*256 + threadIdx.x;
    if (i < N_) atomicAdd(&cnt[ng[i]], 1);
}
__global__ void init_dist_k(const int* __restrict__ ng, const int* __restrict__ cnt,
                            float* __restrict__ dist) {
    int i = blockIdx.x*256 + threadIdx.x;
    if (i < N_) dist[i] = 1.f/(float)cnt[ng[i]];
}

__global__ void prop_softmax_k(const float* __restrict__ R, int step,
                               const float* __restrict__ pe, float* __restrict__ ps) {
    int b = blockIdx.x;
    int p = threadIdx.x >> 5, lane = threadIdx.x & 31;
    const float* instr = R + ((size_t)b*STEPS_ + step)*H_;
    float acc = 0.f;
    for (int h = lane; h < H_; h += 32) acc = fmaf(instr[h], pe[p*H_ + h], acc);
    acc = warp_sum(acc);
    __shared__ float s4[P_];
    if (lane == 0) s4[p] = acc;
    __syncthreads();
    if (threadIdx.x == 0) {
        float m = fmaxf(fmaxf(s4[0], s4[1]), fmaxf(s4[2], s4[3]));
        float e0 = expf(s4[0]-m), e1 = expf(s4[1]-m), e2 = expf(s4[2]-m), e3 = expf(s4[3]-m);
        float inv = 1.f/(e0+e1+e2+e3);
        ps[b*P_+0] = e0*inv; ps[b*P_+1] = e1*inv; ps[b*P_+2] = e2*inv; ps[b*P_+3] = e3*inv;
    }
}

__global__ void node_pass_k(const float* __restrict__ Tr, const float* __restrict__ R, int step,
                            const float* __restrict__ ps, const float* __restrict__ Wst,
                            const int* __restrict__ ng, float* __restrict__ nst) {
    int n = (blockIdx.x*blockDim.x + threadIdx.x) >> 5;
    int lane = threadIdx.x & 31;
    if (n >= N_) return;
    int g = ng[n];
    const float* instr = R + ((size_t)g*STEPS_ + step)*H_;
    float p0 = ps[g*P_+0], p1 = ps[g*P_+1], p2 = ps[g*P_+2];
    const float* T = Tr + (size_t)n*3*H_;
    float acc = 0.f;
    #pragma unroll
    for (int q = 0; q < H_/32; q++) {
        int h = lane + 32*q;
        float tv = p0*T[h] + p1*T[H_+h] + p2*T[2*H_+h];
        float x = instr[h]*tv;
        float e = (x > 0.f) ? x : expm1f(x);
        acc = fmaf(e, Wst[h], acc);
    }
    acc = warp_sum(acc);
    if (lane == 0) nst[n] = acc;
}

__global__ void edge_pass_k(const float* __restrict__ Et, const float* __restrict__ R, int step,
                            const float* __restrict__ Wrel,
                            const int* __restrict__ eg, const int* __restrict__ esrc,
                            const int* __restrict__ edst,
                            const float* __restrict__ dist, float* __restrict__ agg) {
    int e = (blockIdx.x*blockDim.x + threadIdx.x) >> 5;
    int lane = threadIdx.x & 31;
    if (e >= E_) return;
    int g = eg[e];
    const float* instr = R + ((size_t)g*STEPS_ + step)*H_;
    const float* et = Et + (size_t)e*H_;
    float acc = 0.f;
    #pragma unroll
    for (int q = 0; q < H_/32; q++) {
        int h = lane + 32*q;
        float x = instr[h]*et[h];
        float el = (x > 0.f) ? x : expm1f(x);
        acc = fmaf(el, Wrel[h], acc);
    }
    acc = warp_sum(acc);
    if (lane == 0) atomicAdd(&agg[edst[e]], dist[esrc[e]]*acc);
}

__global__ void seg_update_k(const float* __restrict__ nst, const float* __restrict__ agg,
                             const float* __restrict__ ps, float* __restrict__ dist) {
    int g = blockIdx.x, tid = threadIdx.x;
    __shared__ float red[256];
    float v1 = (tid < NPG_) ? nst[g*NPG_ + tid] : -3.4e38f;
    float v2 = (tid < NPG_) ? agg[g*NPG_ + tid] : -3.4e38f;
    red[tid] = v1; __syncthreads();
    for (int o = 128; o > 0; o >>= 1) { if (tid < o) red[tid] = fmaxf(red[tid], red[tid+o]); __syncthreads(); }
    float m1 = red[0]; __syncthreads();
    red[tid] = v2; __syncthreads();
    for (int o = 128; o > 0; o >>= 1) { if (tid < o) red[tid] = fmaxf(red[tid], red[tid+o]); __syncthreads(); }
    float m2 = red[0]; __syncthreads();
    float e1 = (tid < NPG_) ? expf(v1 - m1) : 0.f;
    float e2 = (tid < NPG_) ? expf(v2 - m2) : 0.f;
    red[tid] = e1; __syncthreads();
    for (int o = 128; o > 0; o >>= 1) { if (tid < o) red[tid] += red[tid+o]; __syncthreads(); }
    float s1 = red[0]; __syncthreads();
    red[tid] = e2; __syncthreads();
    for (int o = 128; o > 0; o >>= 1) { if (tid < o) red[tid] += red[tid+o]; __syncthreads(); }
    float s2 = red[0];
    if (tid < NPG_) {
        float r = ps[g*P_ + 3];
        dist[g*NPG_ + tid] = r*(e2/s2) + (1.f - r)*(e1/s1);
    }
}

__global__ void final_agg_k(const float* __restrict__ na, const float* __restrict__ ps,
                            const float* __restrict__ dist, float* __restrict__ agr) {
    int g = blockIdx.x, h = threadIdx.x;
    float p0 = ps[g*P_], p1 = ps[g*P_+1], p2 = ps[g*P_+2];
    float acc = 0.f;
    for (int i = 0; i < NPG_; i++) {
        size_t n = (size_t)g*NPG_ + i;
        const float* a = na + n*3*H_;
        float nf = p0*a[h] + p1*a[H_+h] + p2*a[2*H_+h];
        acc = fmaf(dist[n], nf, acc);
    }
    agr[g*H_ + h] = acc;
}

__global__ void build_qa_k(const float* __restrict__ Q, const float* __restrict__ agr,
                           float* __restrict__ QA) {
    int i = blockIdx.x*256 + threadIdx.x;
    int b = i >> 9, k = i & 511;
    QA[i] = (k < H_) ? Q[b*H_ + k] : agr[b*H_ + (k - H_)];
}

// ---------------- launchers ----------------
static inline void tc_gemm(const float* A, int lda, const float* Bm, int ldb,
                           float* C, int ldc, int M, int N, int K, const float* bias) {
    dim3 g((N + TCB_N - 1)/TCB_N, (M + TCB_M - 1)/TCB_M);
    mma_gemm_k<false><<<g, 256, TC_SMEM_BYTES>>>(A, lda, Bm, ldb, C, ldc, M, N, K,
                                                 bias, nullptr, nullptr);
}
static inline void tc_gemm_expa(const float* A, int lda, const float* Bm, int ldb,
                                float* C, int ldc, int M, int N, int K,
                                const float* rm, const float* ri) {
    dim3 g((N + TCB_N - 1)/TCB_N, (M + TCB_M - 1)/TCB_M);
    mma_gemm_k<true><<<g, 256, TC_SMEM_BYTES>>>(A, lda, Bm, ldb, C, ldc, M, N, K,
                                                nullptr, rm, ri);
}
static inline void gemm64_nt(const float* A, int lda, const float* Bm, int ldb,
                             float* C, int ldc, int M, int N, int K, const float* bias) {
    dim3 g((N + 63)/64, (M + 63)/64);
    gemm_nt_k<64,64,4,4><<<g, 256>>>(A, lda, Bm, ldb, C, ldc, M, N, K, bias);
}

extern "C" void kernel_launch(void* const* d_in, const int* in_sizes, int n_in,
                              void* d_out, int out_size) {
    const float* questions     = (const float*)d_in[0];
    const float* node_attrs    = (const float*)d_in[1];
    const float* edge_attrs    = (const float*)d_in[2];
    const float* vocab         = (const float*)d_in[3];
    const float* default_embed = (const float*)d_in[4];
    const float* W_norm        = (const float*)d_in[5];
    const float* lstm_Wih      = (const float*)d_in[6];
    const float* lstm_Whh      = (const float*)d_in[7];
    const float* lstm_bih      = (const float*)d_in[8];
    const float* lstm_bhh      = (const float*)d_in[9];
    const float* rnn_Wih       = (const float*)d_in[10];
    const float* rnn_Whh       = (const float*)d_in[11];
    const float* rnn_bih       = (const float*)d_in[12];
    const float* rnn_bhh       = (const float*)d_in[13];
    const float* prop_embeds   = (const float*)d_in[14];
    const float* Ws_property   = (const float*)d_in[15];
    const float* W_state       = (const float*)d_in[16];
    const float* W_relation    = (const float*)d_in[17];
    const float* lin_W         = (const float*)d_in[18];
    const float* lin_b         = (const float*)d_in[19];
    const int*   lengths       = (const int*)d_in[20];
    const int*   node_graph    = (const int*)d_in[21];
    const int*   edge_graph    = (const int*)d_in[22];
    const int*   edge_src      = (const int*)d_in[23];
    const int*   edge_dst      = (const int*)d_in[24];
    float* out = (float*)d_out;

    cudaFuncSetAttribute(mma_gemm_k<false>, cudaFuncAttributeMaxDynamicSharedMemorySize, TC_SMEM_BYTES);
    cudaFuncSetAttribute(mma_gemm_k<true>,  cudaFuncAttributeMaxDynamicSharedMemorySize, TC_SMEM_BYTES);

    float* S = nullptr;
    cudaGetSymbolAddress((void**)&S, g_scratch);
    float* Cc   = S + OFF_C;
    float* XW   = S + OFF_XW;
    float* LG   = S + OFF_LOG;
    float* RM   = S + OFF_RM;
    float* RI   = S + OFF_RI;
    float* VT   = S + OFF_VT;
    float* XG   = S + OFF_XG;
    float* G    = S + OFF_G;
    float* Hh   = S + OFF_H;
    float* HX   = S + OFF_HX;
    float* QW   = S + OFF_QW;
    float* HINS = S + OFF_HINS;
    float* Rr   = S + OFF_R;
    float* PS   = S + OFF_PS;
    float* TR   = S + OFF_TR;
    float* ET   = S + OFF_ET;
    float* NS   = S + OFF_NS;
    float* AGG  = S + OFF_AGG;
    float* DIST = S + OFF_DIST;
    int*   CNT  = (int*)(S + OFF_CNT);
    float* AGR  = S + OFF_AGR;
    float* QA   = S + OFF_QA;
    float* WNT  = S + OFF_WNT;
    float* VOCT = S + OFF_VOCT;

    // 0. one-time layout prep
    build_c_k<<<((V_+1)*H_ + 255)/256, 256>>>(vocab, default_embed, Cc);
    transpose_wn_k<<<dim3(8,8), dim3(32,8)>>>(W_norm, WNT);
    vocab_t_k<<<dim3((LDLOG_+31)/32, H_/32), dim3(32,8)>>>(vocab, VOCT);

    // 1. vocab tagging (tensor cores)
    tc_gemm(questions, H_, WNT, H_, XW, H_, BL_, H_, H_, nullptr);
    tc_gemm(XW, H_, Cc, H_, LG, LDLOG_, BL_, V_+1, H_, nullptr);
    row_softmax_k<<<BL_, 256>>>(LG, RM, RI);
    tc_gemm_expa(LG, LDLOG_, VOCT, LDLOG_, VT, H_, BL_, H_, V_, RM, RI);
    vtag_eps_k<<<BL_*H_/256, 256>>>(questions, LG, RM, RI, VT);

    // 2. LSTM encoder
    tc_gemm(VT, H_, lstm_Wih, H_, XG, 4*H_, BL_, 4*H_, H_, lstm_bih);
    zero_k<<<(2*B_*H_ + 255)/256, 256>>>(Hh, 2*B_*H_);
    for (int t = 0; t < L_; t++) {
        gemm64_nt(Hh, H_, lstm_Whh, H_, G, 4*H_, B_, 4*H_, H_, lstm_bhh);
        lstm_gates_k<<<B_*H_/256, 256>>>(XG, G, lengths, t, Hh, S + OFF_CS);
    }

    // 3. decoder RNN + attention
    gemm64_nt(Hh, H_, rnn_Wih, H_, QW, H_, B_, H_, H_, rnn_bih);
    zero_k<<<(B_*H_ + 255)/256, 256>>>(HX, B_*H_);
    for (int s = 0; s < STEPS_; s++)
        dec_step_k<<<B_, H_>>>(QW, rnn_Whh, rnn_bhh, s, HX, HINS);
    attention_k<<<B_, 256>>>(VT, HINS, lengths, Rr);

    // 4. loop-invariant graph transforms (tensor cores)
    for (int p = 0; p < 3; p++)
        tc_gemm(node_attrs + p*H_, 3*H_, Ws_property + (size_t)p*H_*H_, H_,
                TR + p*H_, 3*H_, N_, H_, H_, nullptr);
    tc_gemm(edge_attrs, H_, Ws_property + (size_t)3*H_*H_, H_, ET, H_, E_, H_, H_, nullptr);

    zero_k<<<1, 256>>>((float*)CNT, B_);
    count_nodes_k<<<(N_ + 255)/256, 256>>>(node_graph, CNT);
    init_dist_k<<<(N_ + 255)/256, 256>>>(node_graph, CNT, DIST);

    // 5. 4 reasoning steps
    for (int s = 0; s < STEPS_; s++) {
        prop_softmax_k<<<B_, 128>>>(Rr, s, prop_embeds, PS);
        node_pass_k<<<N_*32/256, 256>>>(TR, Rr, s, PS, W_state, node_graph, NS);
        zero_k<<<(N_ + 255)/256, 256>>>(AGG, N_);
        edge_pass_k<<<E_*32/256, 256>>>(ET, Rr, s, W_relation, edge_graph, edge_src, edge_dst, DIST, AGG);
        seg_update_k<<<B_, 256>>>(NS, AGG, PS, DIST);
    }

    // 6. final aggregation + output projection
    final_agg_k<<<B_, 256>>>(node_attrs, PS, DIST, AGR);
    build_qa_k<<<B_*2*H_/256, 256>>>(Hh, AGR, QA);
    tc_gemm(QA, 2*H_, lin_W, 2*H_, out, OUT_, B_, OUT_, 2*H_, lin_b);
}

// round 6
// speedup vs baseline: 2.3311x; 1.3210x over previous
#include <cuda_runtime.h>
#include <math.h>
#include <stdint.h>

#define B_      256
#define L_      16
#define H_      256
#define V_      5000
#define P_      4
#define NPG_    150
#define STEPS_  4
#define OUT_    2000
#define N_      (B_*NPG_)
#define E_      (N_*4)
#define BL_     (B_*L_)
#define LDLOG_  5008

// ---------------- scratch arena ----------------
static constexpr size_t SZ_C    = (size_t)(V_+1)*H_;
static constexpr size_t SZ_XW   = (size_t)BL_*H_;
static constexpr size_t SZ_LOG  = (size_t)BL_*LDLOG_;
static constexpr size_t SZ_VT   = (size_t)BL_*H_;
static constexpr size_t SZ_XG   = (size_t)BL_*4*H_;
static constexpr size_t SZ_H    = (size_t)B_*H_;
static constexpr size_t SZ_HINS = (size_t)B_*STEPS_*H_;
static constexpr size_t SZ_TR   = (size_t)N_*3*H_;
static constexpr size_t SZ_ET   = (size_t)E_*H_;

static constexpr size_t OFF_C    = 0;
static constexpr size_t OFF_XW   = OFF_C    + SZ_C;
static constexpr size_t OFF_LOG  = OFF_XW   + SZ_XW;
static constexpr size_t OFF_VT   = OFF_LOG  + SZ_LOG;
static constexpr size_t OFF_XG   = OFF_VT   + SZ_VT;
static constexpr size_t OFF_H    = OFF_XG   + SZ_XG;   // LSTM h buf0 (also Q)
static constexpr size_t OFF_CS   = OFF_H    + SZ_H;    // LSTM c
static constexpr size_t OFF_H2   = OFF_CS   + SZ_H;    // LSTM h buf1
static constexpr size_t OFF_R    = OFF_H2   + SZ_H;
static constexpr size_t OFF_PS   = OFF_R    + SZ_HINS;
static constexpr size_t OFF_TR   = OFF_PS   + (size_t)B_*P_;
static constexpr size_t OFF_ET   = OFF_TR   + SZ_TR;
static constexpr size_t OFF_NS   = OFF_ET   + SZ_ET;
static constexpr size_t OFF_AGG  = OFF_NS   + N_;
static constexpr size_t OFF_DIST = OFF_AGG  + N_;
static constexpr size_t OFF_QA   = OFF_DIST + N_;
static constexpr size_t OFF_WNT  = OFF_QA   + (size_t)B_*2*H_;
static constexpr size_t OFF_VOCT = OFF_WNT  + (size_t)H_*H_;
static constexpr size_t OFF_WIHT = OFF_VOCT + (size_t)H_*LDLOG_;
static constexpr size_t OFF_WHHT = OFF_WIHT + (size_t)H_*H_;
static constexpr size_t TOTAL_SCRATCH = OFF_WHHT + (size_t)H_*H_;

__device__ __align__(16) float g_scratch[TOTAL_SCRATCH];

// ---------------- helpers ----------------
__device__ __forceinline__ float warp_sum(float v) {
    #pragma unroll
    for (int o = 16; o > 0; o >>= 1) v += __shfl_down_sync(0xffffffffu, v, o);
    return v;
}
__device__ __forceinline__ float sigmoidf_(float x) { return 1.f / (1.f + expf(-x)); }
__device__ __forceinline__ uint32_t f2tf32(float x) {
    uint32_t u;
    asm("cvt.rna.tf32.f32 %0, %1;" : "=r"(u) : "f"(x));
    return u;
}
__device__ __forceinline__ uint32_t smem_u32(const void* p) {
    uint32_t a;
    asm("{ .reg .u64 t; cvta.to.shared.u64 t, %1; cvt.u32.u64 %0, t; }" : "=r"(a) : "l"(p));
    return a;
}
__device__ __forceinline__ void cp_async16(void* sdst, const void* gsrc, bool pred) {
    uint32_t d = smem_u32(sdst);
    int sz = pred ? 16 : 0;
    asm volatile("cp.async.cg.shared.global [%0], [%1], 16, %2;"
                 :: "r"(d), "l"(gsrc), "r"(sz));
}
__device__ __forceinline__ void cp_commit() {
    asm volatile("cp.async.commit_group;" ::: "memory");
}
template<int N>
__device__ __forceinline__ void cp_wait() {
    asm volatile("cp.async.wait_group %0;" :: "n"(N) : "memory");
}
__device__ __forceinline__ void mma_tf32(float* d, const uint32_t* a, const uint32_t* b) {
    asm volatile(
        "mma.sync.aligned.m16n8k8.row.col.f32.tf32.tf32.f32 "
        "{%0,%1,%2,%3}, {%4,%5,%6,%7}, {%8,%9}, {%0,%1,%2,%3};"
        : "+f"(d[0]), "+f"(d[1]), "+f"(d[2]), "+f"(d[3])
        : "r"(a[0]), "r"(a[1]), "r"(a[2]), "r"(a[3]), "r"(b[0]), "r"(b[1]));
}

// ---------------- tensor-core tf32 GEMM (mma.sync + cp.async) ----------------
// C[m,n] = sum_k A[m,k]*B[n,k] (+bias[n]); 128x64x32 tiles, 256 thr.
#define TCB_M 128
#define TCB_N 64
#define TCB_K 32
#define TAS   36
#define ABUF  (TCB_M*TAS)
#define BBUF  (TCB_N*TAS)
#define TC_SMEM_BYTES ((2*ABUF + 2*BBUF)*4)

__global__ void __launch_bounds__(256, 2)
mma_gemm_k(const float* __restrict__ A, int lda,
           const float* __restrict__ Bm, int ldb,
           float* __restrict__ C, int ldc,
           int M, int N, int K, const float* __restrict__ bias)
{
    extern __shared__ float smf[];
    float* As = smf;
    float* Bs = smf + 2*ABUF;
    const int tid  = threadIdx.x;
    const int wid  = tid >> 5, lane = tid & 31;
    const int g    = lane >> 2, t4 = lane & 3;
    const int wm   = wid & 3, wn = wid >> 2;
    const int bm   = blockIdx.y * TCB_M;
    const int bn   = blockIdx.x * TCB_N;

    float acc[2][4][4];
    #pragma unroll
    for (int i = 0; i < 2; i++)
        #pragma unroll
        for (int j = 0; j < 4; j++)
            #pragma unroll
            for (int q = 0; q < 4; q++) acc[i][j][q] = 0.f;

    const int arow = tid >> 3, acc4 = (tid & 7) << 2;

    auto issue_chunk = [&](int c) {
        int k0 = c * TCB_K;
        int buf = c & 1;
        #pragma unroll
        for (int i = 0; i < 4; i++) {
            int row = arow + i*32;
            int gm = bm + row, gk = k0 + acc4;
            cp_async16(As + buf*ABUF + row*TAS + acc4,
                       A + (size_t)gm*lda + gk, (gm < M) && (gk < K));
        }
        #pragma unroll
        for (int i = 0; i < 2; i++) {
            int row = arow + i*32;
            int gn = bn + row, gk = k0 + acc4;
            cp_async16(Bs + buf*BBUF + row*TAS + acc4,
                       Bm + (size_t)gn*ldb + gk, (gn < N) && (gk < K));
        }
        cp_commit();
    };

    const int nch = (K + TCB_K - 1) / TCB_K;
    issue_chunk(0);

    for (int c = 0; c < nch; c++) {
        if (c + 1 < nch) { issue_chunk(c + 1); cp_wait<1>(); }
        else             { cp_wait<0>(); }
        __syncthreads();

        const float* Ab = As + (c & 1)*ABUF;
        const float* Bb = Bs + (c & 1)*BBUF;
        #pragma unroll
        for (int ks = 0; ks < 4; ks++) {
            uint32_t af[2][4], bf[4][2];
            #pragma unroll
            for (int mt = 0; mt < 2; mt++) {
                int r0 = (wm*32 + mt*16 + g)*TAS + ks*8 + t4;
                af[mt][0] = f2tf32(Ab[r0]);
                af[mt][1] = f2tf32(Ab[r0 + 8*TAS]);
                af[mt][2] = f2tf32(Ab[r0 + 4]);
                af[mt][3] = f2tf32(Ab[r0 + 8*TAS + 4]);
            }
            #pragma unroll
            for (int nt = 0; nt < 4; nt++) {
                int rb = (wn*32 + nt*8 + g)*TAS + ks*8 + t4;
                bf[nt][0] = f2tf32(Bb[rb]);
                bf[nt][1] = f2tf32(Bb[rb + 4]);
            }
            #pragma unroll
            for (int mt = 0; mt < 2; mt++)
                #pragma unroll
                for (int nt = 0; nt < 4; nt++)
                    mma_tf32(acc[mt][nt], af[mt], bf[nt]);
        }
        __syncthreads();
    }

    #pragma unroll
    for (int mt = 0; mt < 2; mt++) {
        int row0 = bm + wm*32 + mt*16 + g;
        #pragma unroll
        for (int nt = 0; nt < 4; nt++) {
            int col0 = bn + wn*32 + nt*8 + t4*2;
            float b0v = 0.f, b1v = 0.f;
            if (bias) {
                if (col0     < N) b0v = bias[col0];
                if (col0 + 1 < N) b1v = bias[col0+1];
            }
            if (row0 < M) {
                if (col0     < N) C[(size_t)row0*ldc + col0    ] = acc[mt][nt][0] + b0v;
                if (col0 + 1 < N) C[(size_t)row0*ldc + col0 + 1] = acc[mt][nt][1] + b1v;
            }
            if (row0 + 8 < M) {
                if (col0     < N) C[(size_t)(row0+8)*ldc + col0    ] = acc[mt][nt][2] + b0v;
                if (col0 + 1 < N) C[(size_t)(row0+8)*ldc + col0 + 1] = acc[mt][nt][3] + b1v;
            }
        }
    }
}

// ---------------- fused LSTM step ----------------
// Block: 64 b-rows x 16 hh-cols (x4 gates gathered as 64 B-rows). Grid (16,4).
__global__ void __launch_bounds__(256)
lstm_step_k(const float* __restrict__ hin,       // [B,H] prev h
            float* __restrict__ hout,            // [B,H] next h
            float* __restrict__ cst,             // [B,H] cell (in place)
            const float* __restrict__ Xg,        // [B*L, 4H] (incl bih)
            const float* __restrict__ Whh,       // [4H, H]
            const float* __restrict__ bhh,       // [4H]
            const int* __restrict__ lengths, int t)
{
    __shared__ float As[8][64];
    __shared__ float Bs[8][64];
    __shared__ float Cs[64][65];
    const int tid = threadIdx.x;
    const int hh0 = blockIdx.x * 16;
    const int bm  = blockIdx.y * 64;
    const int tx = tid & 15, ty = tid >> 4;   // 16x16 thread grid, 4x4 per thread

    float acc[4][4];
    #pragma unroll
    for (int i = 0; i < 4; i++)
        #pragma unroll
        for (int j = 0; j < 4; j++) acc[i][j] = 0.f;

    for (int k0 = 0; k0 < H_; k0 += 8) {
        if (tid < 128) {
            int m = tid >> 1, kq = (tid & 1)*4;
            float4 v = *reinterpret_cast<const float4*>(hin + (size_t)(bm+m)*H_ + k0 + kq);
            As[kq+0][m]=v.x; As[kq+1][m]=v.y; As[kq+2][m]=v.z; As[kq+3][m]=v.w;
        } else {
            int it = tid - 128;
            int j = it >> 1, kq = (it & 1)*4;
            int gn = (j >> 4)*H_ + hh0 + (j & 15);
            float4 v = *reinterpret_cast<const float4*>(Whh + (size_t)gn*H_ + k0 + kq);
            Bs[kq+0][j]=v.x; Bs[kq+1][j]=v.y; Bs[kq+2][j]=v.z; Bs[kq+3][j]=v.w;
        }
        __syncthreads();
        #pragma unroll
        for (int k = 0; k < 8; k++) {
            float ar[4], br[4];
            #pragma unroll
            for (int i = 0; i < 4; i++) ar[i] = As[k][ty*4+i];
            #pragma unroll
            for (int j = 0; j < 4; j++) br[j] = Bs[k][tx*4+j];
            #pragma unroll
            for (int i = 0; i < 4; i++)
                #pragma unroll
                for (int j = 0; j < 4; j++)
                    acc[i][j] = fmaf(ar[i], br[j], acc[i][j]);
        }
        __syncthreads();
    }
    #pragma unroll
    for (int i = 0; i < 4; i++)
        #pragma unroll
        for (int j = 0; j < 4; j++)
            Cs[ty*4+i][tx*4+j] = acc[i][j];
    __syncthreads();

    #pragma unroll
    for (int i = 0; i < 4; i++) {
        int cell = i*256 + tid;           // 1024 cells: 64 b x 16 hh
        int b_l = cell >> 4, hh_l = cell & 15;
        int b = bm + b_l, hh = hh0 + hh_l;
        const float* xrow = Xg + (size_t)(b*L_ + t)*(4*H_);
        float gi = Cs[b_l][0*16+hh_l] + xrow[hh]        + bhh[hh];
        float gf = Cs[b_l][1*16+hh_l] + xrow[H_+hh]     + bhh[H_+hh];
        float gc = Cs[b_l][2*16+hh_l] + xrow[2*H_+hh]   + bhh[2*H_+hh];
        float go = Cs[b_l][3*16+hh_l] + xrow[3*H_+hh]   + bhh[3*H_+hh];
        size_t idx = (size_t)b*H_ + hh;
        float hold = hin[idx];
        if (t < lengths[b]) {
            float cn = sigmoidf_(gf)*cst[idx] + sigmoidf_(gi)*tanhf(gc);
            cst[idx] = cn;
            hout[idx] = sigmoidf_(go)*tanhf(cn);
        } else {
            hout[idx] = hold;
        }
    }
}

// ---------------- fused decoder RNN + attention (block per b) ----------------
__global__ void __launch_bounds__(256)
dec_attn_k(const float* __restrict__ Q,         // [B,H]
           const float* __restrict__ WihT,      // [H,H] (k-major)
           const float* __restrict__ WhhT,      // [H,H]
           const float* __restrict__ bih, const float* __restrict__ bhh,
           const float* __restrict__ Vt,        // [B,L,H]
           const int* __restrict__ lengths,
           float* __restrict__ R)               // [B,STEPS,H]
{
    int b = blockIdx.x, tid = threadIdx.x;
    __shared__ float shh[H_], sQ[H_], sh[H_];
    __shared__ float sV[L_][H_];
    __shared__ float sHins[STEPS_][H_];
    __shared__ float satt[STEPS_][L_];

    shh[tid] = Q[(size_t)b*H_ + tid];
    for (int i = tid; i < L_*H_; i += 256) sV[i>>8][i&255] = Vt[(size_t)b*L_*H_ + i];
    __syncthreads();

    float acc = bih[tid];
    #pragma unroll 8
    for (int k = 0; k < H_; k++) acc = fmaf(shh[k], WihT[(size_t)k*H_ + tid], acc);
    sQ[tid] = acc;
    sh[tid] = 0.f;
    __syncthreads();

    for (int s = 0; s < STEPS_; s++) {
        float v = sQ[tid] + bhh[tid];
        #pragma unroll 8
        for (int k = 0; k < H_; k++) v = fmaf(sh[k], WhhT[(size_t)k*H_ + tid], v);
        v = fmaxf(v, 0.f);
        __syncthreads();
        sh[tid] = v;
        sHins[s][tid] = v;
        __syncthreads();
    }

    int warp = tid >> 5, lane = tid & 31;
    for (int pid = warp; pid < STEPS_*L_; pid += 8) {
        int s = pid >> 4, l = pid & 15;
        float a = 0.f;
        #pragma unroll
        for (int q = 0; q < H_/32; q++) a = fmaf(sHins[s][lane+32*q], sV[l][lane+32*q], a);
        a = warp_sum(a);
        if (lane == 0) satt[s][l] = a;
    }
    __syncthreads();
    if (tid < STEPS_) {
        int len = lengths[b];
        float m = -3.4e38f;
        for (int l = 0; l < len; l++) m = fmaxf(m, satt[tid][l]);
        float s = 0.f;
        for (int l = 0; l < len; l++) { float e = expf(satt[tid][l]-m); satt[tid][l]=e; s+=e; }
        float inv = 1.f/s;
        for (int l = 0; l < L_; l++) satt[tid][l] = (l < len) ? satt[tid][l]*inv : 0.f;
    }
    __syncthreads();
    for (int s = 0; s < STEPS_; s++) {
        float a2 = 0.f;
        #pragma unroll
        for (int l = 0; l < L_; l++) a2 = fmaf(satt[s][l], sV[l][tid], a2);
        R[((size_t)b*STEPS_ + s)*H_ + tid] = a2;
    }
}

// ---------------- small kernels ----------------
__global__ void build_c_k(const float* __restrict__ vocab, const float* __restrict__ de,
                          float* __restrict__ Cc) {
    int i = blockIdx.x*256 + threadIdx.x;
    if (i < (V_+1)*H_) Cc[i] = (i < V_*H_) ? vocab[i] : de[i - (size_t)V_*H_];
}

__global__ void transpose_wn_k(const float* __restrict__ W, float* __restrict__ WT) {
    __shared__ float t[32][33];
    int rb = blockIdx.y*32, cb = blockIdx.x*32;
    int x = threadIdx.x, y = threadIdx.y;
    for (int j = y; j < 32; j += 8) t[j][x] = W[(size_t)(rb+j)*H_ + cb + x];
    __syncthreads();
    for (int j = y; j < 32; j += 8) WT[(size_t)(cb+j)*H_ + rb + x] = t[x][j];
}

__global__ void vocab_t_k(const float* __restrict__ vocab, float* __restrict__ vt) {
    __shared__ float t[32][33];
    int vb = blockIdx.x*32, hb = blockIdx.y*32;
    int x = threadIdx.x, y = threadIdx.y;
    for (int j = y; j < 32; j += 8) {
        int v = vb + j;
        t[j][x] = (v < V_) ? vocab[(size_t)v*H_ + hb + x] : 0.f;
    }
    __syncthreads();
    for (int j = y; j < 32; j += 8) {
        int v = vb + x;
        if (v < LDLOG_) vt[(size_t)(hb+j)*LDLOG_ + v] = t[x][j];
    }
}

__global__ void zero_k(float* __restrict__ p, int n) {
    int i = blockIdx.x*256 + threadIdx.x;
    if (i < n) p[i] = 0.f;
}

// 3-pass fused row softmax: computes max, sum, then overwrites row with prob.
__global__ void row_softmax_w_k(float* __restrict__ Lg) {
    int r = blockIdx.x;
    float* row = Lg + (size_t)r*LDLOG_;
    __shared__ float red[256];
    float m = -3.4e38f;
    for (int j = threadIdx.x; j < V_+1; j += 256) m = fmaxf(m, row[j]);
    red[threadIdx.x] = m; __syncthreads();
    for (int o = 128; o > 0; o >>= 1) {
        if (threadIdx.x < o) red[threadIdx.x] = fmaxf(red[threadIdx.x], red[threadIdx.x+o]);
        __syncthreads();
    }
    float M = red[0]; __syncthreads();
    float s = 0.f;
    for (int j = threadIdx.x; j < V_+1; j += 256) s += expf(row[j] - M);
    red[threadIdx.x] = s; __syncthreads();
    for (int o = 128; o > 0; o >>= 1) {
        if (threadIdx.x < o) red[threadIdx.x] += red[threadIdx.x+o];
        __syncthreads();
    }
    float inv = 1.f/red[0];
    for (int j = threadIdx.x; j < V_+1; j += 256)
        row[j] = expf(row[j] - M) * inv;
}

__global__ void vtag_eps_k(const float* __restrict__ words, const float* __restrict__ Lg,
                           float* __restrict__ Vt) {
    int i = blockIdx.x*256 + threadIdx.x;
    int r = i >> 8;
    float w = Lg[(size_t)r*LDLOG_ + V_];
    Vt[i] += w * words[i];
}

__global__ void init_dist_k(float* __restrict__ dist) {
    int i = blockIdx.x*256 + threadIdx.x;
    if (i < N_) dist[i] = 1.f/(float)NPG_;
}

// prop_softmax (blocks 0..B_-1) + zero AGG (rest)
#define ZB_ ((N_ + 255)/256)
__global__ void prep_step_k(const float* __restrict__ R, int step,
                            const float* __restrict__ pe, float* __restrict__ ps,
                            float* __restrict__ agg) {
    int bid = blockIdx.x, tid = threadIdx.x;
    if (bid < B_) {
        __shared__ float s4[P_];
        if (tid < 128) {
            int p = tid >> 5, lane = tid & 31;
            const float* instr = R + ((size_t)bid*STEPS_ + step)*H_;
            float acc = 0.f;
            for (int h = lane; h < H_; h += 32) acc = fmaf(instr[h], pe[p*H_ + h], acc);
            acc = warp_sum(acc);
            if (lane == 0) s4[p] = acc;
        }
        __syncthreads();
        if (tid == 0) {
            float m = fmaxf(fmaxf(s4[0], s4[1]), fmaxf(s4[2], s4[3]));
            float e0 = expf(s4[0]-m), e1 = expf(s4[1]-m), e2 = expf(s4[2]-m), e3 = expf(s4[3]-m);
            float inv = 1.f/(e0+e1+e2+e3);
            ps[bid*P_+0]=e0*inv; ps[bid*P_+1]=e1*inv; ps[bid*P_+2]=e2*inv; ps[bid*P_+3]=e3*inv;
        }
    } else {
        int i = (bid - B_)*256 + tid;
        if (i < N_) agg[i] = 0.f;
    }
}

// node pass (blocks 0..NODE_BLKS-1) + edge pass (rest); warp per item.
#define NODE_BLKS (N_/8)
#define EDGE_BLKS (E_/8)
__global__ void node_edge_k(const float* __restrict__ Tr, const float* __restrict__ Et,
                            const float* __restrict__ R, int step,
                            const float* __restrict__ ps,
                            const float* __restrict__ Wst, const float* __restrict__ Wrel,
                            const int* __restrict__ ng, const int* __restrict__ eg,
                            const int* __restrict__ esrc, const int* __restrict__ edst,
                            const float* __restrict__ dist,
                            float* __restrict__ nst, float* __restrict__ agg) {
    int bid = blockIdx.x;
    int warp = threadIdx.x >> 5, lane = threadIdx.x & 31;
    if (bid < NODE_BLKS) {
        int n = bid*8 + warp;
        int g = ng[n];
        const float* instr = R + ((size_t)g*STEPS_ + step)*H_;
        float p0 = ps[g*P_+0], p1 = ps[g*P_+1], p2 = ps[g*P_+2];
        const float* T = Tr + (size_t)n*3*H_;
        float acc = 0.f;
        #pragma unroll
        for (int q = 0; q < H_/32; q++) {
            int h = lane + 32*q;
            float tv = p0*T[h] + p1*T[H_+h] + p2*T[2*H_+h];
            float x = instr[h]*tv;
            float e = (x > 0.f) ? x : expm1f(x);
            acc = fmaf(e, Wst[h], acc);
        }
        acc = warp_sum(acc);
        if (lane == 0) nst[n] = acc;
    } else {
        int e = (bid - NODE_BLKS)*8 + warp;
        int g = eg[e];
        const float* instr = R + ((size_t)g*STEPS_ + step)*H_;
        const float* et = Et + (size_t)e*H_;
        float acc = 0.f;
        #pragma unroll
        for (int q = 0; q < H_/32; q++) {
            int h = lane + 32*q;
            float x = instr[h]*et[h];
            float el = (x > 0.f) ? x : expm1f(x);
            acc = fmaf(el, Wrel[h], acc);
        }
        acc = warp_sum(acc);
        if (lane == 0) atomicAdd(&agg[edst[e]], dist[esrc[e]]*acc);
    }
}

__global__ void seg_update_k(const float* __restrict__ nst, const float* __restrict__ agg,
                             const float* __restrict__ ps, float* __restrict__ dist) {
    int g = blockIdx.x, tid = threadIdx.x;
    __shared__ float red[256];
    float v1 = (tid < NPG_) ? nst[g*NPG_ + tid] : -3.4e38f;
    float v2 = (tid < NPG_) ? agg[g*NPG_ + tid] : -3.4e38f;
    red[tid] = v1; __syncthreads();
    for (int o = 128; o > 0; o >>= 1) { if (tid < o) red[tid] = fmaxf(red[tid], red[tid+o]); __syncthreads(); }
    float m1 = red[0]; __syncthreads();
    red[tid] = v2; __syncthreads();
    for (int o = 128; o > 0; o >>= 1) { if (tid < o) red[tid] = fmaxf(red[tid], red[tid+o]); __syncthreads(); }
    float m2 = red[0]; __syncthreads();
    float e1 = (tid < NPG_) ? expf(v1 - m1) : 0.f;
    float e2 = (tid < NPG_) ? expf(v2 - m2) : 0.f;
    red[tid] = e1; __syncthreads();
    for (int o = 128; o > 0; o >>= 1) { if (tid < o) red[tid] += red[tid+o]; __syncthreads(); }
    float s1 = red[0]; __syncthreads();
    red[tid] = e2; __syncthreads();
    for (int o = 128; o > 0; o >>= 1) { if (tid < o) red[tid] += red[tid+o]; __syncthreads(); }
    float s2 = red[0];
    if (tid < NPG_) {
        float r = ps[g*P_ + 3];
        dist[g*NPG_ + tid] = r*(e2/s2) + (1.f - r)*(e1/s1);
    }
}

__global__ void final_agg_qa_k(const float* __restrict__ na, const float* __restrict__ ps,
                               const float* __restrict__ dist, const float* __restrict__ Q,
                               float* __restrict__ QA) {
    int g = blockIdx.x, h = threadIdx.x;
    float p0 = ps[g*P_], p1 = ps[g*P_+1], p2 = ps[g*P_+2];
    float acc = 0.f;
    for (int i = 0; i < NPG_; i++) {
        size_t n = (size_t)g*NPG_ + i;
        const float* a = na + n*3*H_;
        float nf = p0*a[h] + p1*a[H_+h] + p2*a[2*H_+h];
        acc = fmaf(dist[n], nf, acc);
    }
    QA[(size_t)g*2*H_ + h]      = Q[(size_t)g*H_ + h];
    QA[(size_t)g*2*H_ + H_ + h] = acc;
}

// ---------------- launchers ----------------
static inline void tc_gemm(const float* A, int lda, const float* Bm, int ldb,
                           float* C, int ldc, int M, int N, int K, const float* bias) {
    dim3 g((N + TCB_N - 1)/TCB_N, (M + TCB_M - 1)/TCB_M);
    mma_gemm_k<<<g, 256, TC_SMEM_BYTES>>>(A, lda, Bm, ldb, C, ldc, M, N, K, bias);
}

extern "C" void kernel_launch(void* const* d_in, const int* in_sizes, int n_in,
                              void* d_out, int out_size) {
    const float* questions     = (const float*)d_in[0];
    const float* node_attrs    = (const float*)d_in[1];
    const float* edge_attrs    = (const float*)d_in[2];
    const float* vocab         = (const float*)d_in[3];
    const float* default_embed = (const float*)d_in[4];
    const float* W_norm        = (const float*)d_in[5];
    const float* lstm_Wih      = (const float*)d_in[6];
    const float* lstm_Whh      = (const float*)d_in[7];
    const float* lstm_bih      = (const float*)d_in[8];
    const float* lstm_bhh      = (const float*)d_in[9];
    const float* rnn_Wih       = (const float*)d_in[10];
    const float* rnn_Whh       = (const float*)d_in[11];
    const float* rnn_bih       = (const float*)d_in[12];
    const float* rnn_bhh       = (const float*)d_in[13];
    const float* prop_embeds   = (const float*)d_in[14];
    const float* Ws_property   = (const float*)d_in[15];
    const float* W_state       = (const float*)d_in[16];
    const float* W_relation    = (const float*)d_in[17];
    const float* lin_W         = (const float*)d_in[18];
    const float* lin_b         = (const float*)d_in[19];
    const int*   lengths       = (const int*)d_in[20];
    const int*   node_graph    = (const int*)d_in[21];
    const int*   edge_graph    = (const int*)d_in[22];
    const int*   edge_src      = (const int*)d_in[23];
    const int*   edge_dst      = (const int*)d_in[24];
    float* out = (float*)d_out;

    cudaFuncSetAttribute(mma_gemm_k, cudaFuncAttributeMaxDynamicSharedMemorySize, TC_SMEM_BYTES);

    float* S = nullptr;
    cudaGetSymbolAddress((void**)&S, g_scratch);
    float* Cc   = S + OFF_C;
    float* XW   = S + OFF_XW;
    float* LG   = S + OFF_LOG;
    float* VT   = S + OFF_VT;
    float* XG   = S + OFF_XG;
    float* H0   = S + OFF_H;
    float* Cst  = S + OFF_CS;
    float* H1   = S + OFF_H2;
    float* Rr   = S + OFF_R;
    float* PS   = S + OFF_PS;
    float* TR   = S + OFF_TR;
    float* ET   = S + OFF_ET;
    float* NS   = S + OFF_NS;
    float* AGG  = S + OFF_AGG;
    float* DIST = S + OFF_DIST;
    float* QA   = S + OFF_QA;
    float* WNT  = S + OFF_WNT;
    float* VOCT = S + OFF_VOCT;
    float* WIHT = S + OFF_WIHT;
    float* WHHT = S + OFF_WHHT;

    // 0. one-time layout prep
    build_c_k<<<((V_+1)*H_ + 255)/256, 256>>>(vocab, default_embed, Cc);
    transpose_wn_k<<<dim3(8,8), dim3(32,8)>>>(W_norm, WNT);
    transpose_wn_k<<<dim3(8,8), dim3(32,8)>>>(rnn_Wih, WIHT);
    transpose_wn_k<<<dim3(8,8), dim3(32,8)>>>(rnn_Whh, WHHT);
    vocab_t_k<<<dim3((LDLOG_+31)/32, H_/32), dim3(32,8)>>>(vocab, VOCT);

    // 1. vocab tagging
    tc_gemm(questions, H_, WNT, H_, XW, H_, BL_, H_, H_, nullptr);
    tc_gemm(XW, H_, Cc, H_, LG, LDLOG_, BL_, V_+1, H_, nullptr);
    row_softmax_w_k<<<BL_, 256>>>(LG);            // LG now holds probabilities
    tc_gemm(LG, LDLOG_, VOCT, LDLOG_, VT, H_, BL_, H_, V_, nullptr);
    vtag_eps_k<<<BL_*H_/256, 256>>>(questions, LG, VT);

    // 2. LSTM encoder (fused step kernel, ping-pong h)
    tc_gemm(VT, H_, lstm_Wih, H_, XG, 4*H_, BL_, 4*H_, H_, lstm_bih);
    zero_k<<<(2*B_*H_ + 255)/256, 256>>>(H0, 2*B_*H_);   // H0 and Cst contiguous
    for (int t = 0; t < L_; t++) {
        const float* hin = (t & 1) ? H1 : H0;
        float* hout      = (t & 1) ? H0 : H1;
        lstm_step_k<<<dim3(16,4), 256>>>(hin, hout, Cst, XG, lstm_Whh, lstm_bhh, lengths, t);
    }
    // L_=16 even -> final h in H0

    // 3. fused decoder + attention
    dec_attn_k<<<B_, 256>>>(H0, WIHT, WHHT, rnn_bih, rnn_bhh, VT, lengths, Rr);

    // 4. loop-invariant graph transforms
    for (int p = 0; p < 3; p++)
        tc_gemm(node_attrs + p*H_, 3*H_, Ws_property + (size_t)p*H_*H_, H_,
                TR + p*H_, 3*H_, N_, H_, H_, nullptr);
    tc_gemm(edge_attrs, H_, Ws_property + (size_t)3*H_*H_, H_, ET, H_, E_, H_, H_, nullptr);

    init_dist_k<<<(N_ + 255)/256, 256>>>(DIST);

    // 5. 4 reasoning steps (3 launches each)
    for (int s = 0; s < STEPS_; s++) {
        prep_step_k<<<B_ + ZB_, 256>>>(Rr, s, prop_embeds, PS, AGG);
        node_edge_k<<<NODE_BLKS + EDGE_BLKS, 256>>>(TR, ET, Rr, s, PS, W_state, W_relation,
                                                    node_graph, edge_graph, edge_src, edge_dst,
                                                    DIST, NS, AGG);
        seg_update_k<<<B_, 256>>>(NS, AGG, PS, DIST);
    }

    // 6. final aggregation + output projection
    final_agg_qa_k<<<B_, 256>>>(node_attrs, PS, DIST, H0, QA);
    tc_gemm(QA, 2*H_, lin_W, 2*H_, out, OUT_, B_, OUT_, 2*H_, lin_b);
}

// round 7
// speedup vs baseline: 2.5437x; 1.0912x over previous
#include <cuda_runtime.h>
#include <math.h>
#include <stdint.h>

#define B_      256
#define L_      16
#define H_      256
#define V_      5000
#define P_      4
#define NPG_    150
#define STEPS_  4
#define OUT_    2000
#define N_      (B_*NPG_)
#define E_      (N_*4)
#define BL_     (B_*L_)
#define LDLOG_  5008

// ---------------- scratch arena ----------------
static constexpr size_t SZ_C    = (size_t)(V_+1)*H_;
static constexpr size_t SZ_XW   = (size_t)BL_*H_;
static constexpr size_t SZ_LOG  = (size_t)BL_*LDLOG_;
static constexpr size_t SZ_VT   = (size_t)BL_*H_;
static constexpr size_t SZ_XG   = (size_t)BL_*4*H_;
static constexpr size_t SZ_H    = (size_t)B_*H_;
static constexpr size_t SZ_HINS = (size_t)B_*STEPS_*H_;
static constexpr size_t SZ_TR   = (size_t)N_*3*H_;
static constexpr size_t SZ_ET   = (size_t)E_*H_;

static constexpr size_t OFF_C    = 0;
static constexpr size_t OFF_XW   = OFF_C    + SZ_C;
static constexpr size_t OFF_LOG  = OFF_XW   + SZ_XW;
static constexpr size_t OFF_VT   = OFF_LOG  + SZ_LOG;
static constexpr size_t OFF_XG   = OFF_VT   + SZ_VT;
static constexpr size_t OFF_H    = OFF_XG   + SZ_XG;
static constexpr size_t OFF_CS   = OFF_H    + SZ_H;
static constexpr size_t OFF_H2   = OFF_CS   + SZ_H;
static constexpr size_t OFF_R    = OFF_H2   + SZ_H;
static constexpr size_t OFF_PS   = OFF_R    + SZ_HINS;
static constexpr size_t OFF_TR   = OFF_PS   + (size_t)B_*P_;
static constexpr size_t OFF_ET   = OFF_TR   + SZ_TR;
static constexpr size_t OFF_NS   = OFF_ET   + SZ_ET;
static constexpr size_t OFF_AGG  = OFF_NS   + N_;
static constexpr size_t OFF_DIST = OFF_AGG  + N_;
static constexpr size_t OFF_QA   = OFF_DIST + N_;
static constexpr size_t OFF_WNT  = OFF_QA   + (size_t)B_*2*H_;
static constexpr size_t OFF_VOCT = OFF_WNT  + (size_t)H_*H_;
static constexpr size_t OFF_WIHT = OFF_VOCT + (size_t)H_*LDLOG_;
static constexpr size_t OFF_WHHT = OFF_WIHT + (size_t)H_*H_;
static constexpr size_t TOTAL_SCRATCH = OFF_WHHT + (size_t)H_*H_;

__device__ __align__(16) float g_scratch[TOTAL_SCRATCH];

// ---------------- helpers ----------------
__device__ __forceinline__ float warp_sum(float v) {
    #pragma unroll
    for (int o = 16; o > 0; o >>= 1) v += __shfl_down_sync(0xffffffffu, v, o);
    return v;
}
__device__ __forceinline__ float sigmoidf_(float x) { return 1.f / (1.f + expf(-x)); }
__device__ __forceinline__ uint32_t f2tf32(float x) {
    uint32_t u;
    asm("cvt.rna.tf32.f32 %0, %1;" : "=r"(u) : "f"(x));
    return u;
}
__device__ __forceinline__ uint32_t smem_u32(const void* p) {
    uint32_t a;
    asm("{ .reg .u64 t; cvta.to.shared.u64 t, %1; cvt.u32.u64 %0, t; }" : "=r"(a) : "l"(p));
    return a;
}
__device__ __forceinline__ void cp_async16(void* sdst, const void* gsrc, bool pred) {
    uint32_t d = smem_u32(sdst);
    int sz = pred ? 16 : 0;
    asm volatile("cp.async.cg.shared.global [%0], [%1], 16, %2;"
                 :: "r"(d), "l"(gsrc), "r"(sz));
}
__device__ __forceinline__ void cp_commit() {
    asm volatile("cp.async.commit_group;" ::: "memory");
}
template<int N>
__device__ __forceinline__ void cp_wait() {
    asm volatile("cp.async.wait_group %0;" :: "n"(N) : "memory");
}
__device__ __forceinline__ void mma_tf32(float* d, const uint32_t* a, const uint32_t* b) {
    asm volatile(
        "mma.sync.aligned.m16n8k8.row.col.f32.tf32.tf32.f32 "
        "{%0,%1,%2,%3}, {%4,%5,%6,%7}, {%8,%9}, {%0,%1,%2,%3};"
        : "+f"(d[0]), "+f"(d[1]), "+f"(d[2]), "+f"(d[3])
        : "r"(a[0]), "r"(a[1]), "r"(a[2]), "r"(a[3]), "r"(b[0]), "r"(b[1]));
}

// ---------------- tensor-core tf32 GEMM: CTA 128x128x32, warp 64x64 ----------------
// C[m,n] = sum_k A[m,k]*B[n,k] (+bias[n]).  splitk>1: atomicAdd into pre-zeroed C,
// bias contributed only by blockIdx.z==0.
#define GB_M 128
#define GB_N 128
#define GB_K 32
#define GTS  36
#define GABUF (GB_M*GTS)
#define GBBUF (GB_N*GTS)
#define G_SMEM_BYTES ((2*GABUF + 2*GBBUF)*4)

__global__ void __launch_bounds__(128, 2)
mma_gemm_k(const float* __restrict__ A, int lda,
           const float* __restrict__ Bm, int ldb,
           float* __restrict__ C, int ldc,
           int M, int N, int K, const float* __restrict__ bias, int splitk)
{
    extern __shared__ float smf[];
    float* As = smf;
    float* Bs = smf + 2*GABUF;
    const int tid  = threadIdx.x;
    const int wid  = tid >> 5, lane = tid & 31;
    const int g    = lane >> 2, t4 = lane & 3;
    const int wm   = wid & 1, wn = wid >> 1;
    const int bm   = blockIdx.y * GB_M;
    const int bn   = blockIdx.x * GB_N;

    int kslen = K, kbeg = 0, kend = K;
    if (splitk > 1) {
        kslen = (((K + splitk - 1) / splitk) + 3) & ~3;
        kbeg  = blockIdx.z * kslen;
        kend  = min(K, kbeg + kslen);
    }

    float acc[4][8][4];
    #pragma unroll
    for (int i = 0; i < 4; i++)
        #pragma unroll
        for (int j = 0; j < 8; j++)
            #pragma unroll
            for (int q = 0; q < 4; q++) acc[i][j][q] = 0.f;

    const int lrow = tid >> 3, lc4 = (tid & 7) << 2;  // 16 rows per pass, 8 passes

    auto issue_chunk = [&](int c) {
        int k0 = kbeg + c * GB_K;
        int buf = c & 1;
        #pragma unroll
        for (int i = 0; i < 8; i++) {
            int row = lrow + i*16;
            int gm = bm + row, gk = k0 + lc4;
            cp_async16(As + buf*GABUF + row*GTS + lc4,
                       A + (size_t)gm*lda + gk, (gm < M) && (gk < kend));
        }
        #pragma unroll
        for (int i = 0; i < 8; i++) {
            int row = lrow + i*16;
            int gn = bn + row, gk = k0 + lc4;
            cp_async16(Bs + buf*GBBUF + row*GTS + lc4,
                       Bm + (size_t)gn*ldb + gk, (gn < N) && (gk < kend));
        }
        cp_commit();
    };

    const int nch = (kend - kbeg + GB_K - 1) / GB_K;
    issue_chunk(0);

    for (int c = 0; c < nch; c++) {
        if (c + 1 < nch) { issue_chunk(c + 1); cp_wait<1>(); }
        else             { cp_wait<0>(); }
        __syncthreads();

        const float* Ab = As + (c & 1)*GABUF;
        const float* Bb = Bs + (c & 1)*GBBUF;
        #pragma unroll
        for (int ks = 0; ks < 4; ks++) {
            uint32_t af[4][4], bf[8][2];
            #pragma unroll
            for (int mt = 0; mt < 4; mt++) {
                int r0 = (wm*64 + mt*16 + g)*GTS + ks*8 + t4;
                af[mt][0] = f2tf32(Ab[r0]);
                af[mt][1] = f2tf32(Ab[r0 + 8*GTS]);
                af[mt][2] = f2tf32(Ab[r0 + 4]);
                af[mt][3] = f2tf32(Ab[r0 + 8*GTS + 4]);
            }
            #pragma unroll
            for (int nt = 0; nt < 8; nt++) {
                int rb = (wn*64 + nt*8 + g)*GTS + ks*8 + t4;
                bf[nt][0] = f2tf32(Bb[rb]);
                bf[nt][1] = f2tf32(Bb[rb + 4]);
            }
            #pragma unroll
            for (int mt = 0; mt < 4; mt++)
                #pragma unroll
                for (int nt = 0; nt < 8; nt++)
                    mma_tf32(acc[mt][nt], af[mt], bf[nt]);
        }
        __syncthreads();
    }

    const bool addb = (bias != nullptr) && (blockIdx.z == 0);
    #pragma unroll
    for (int mt = 0; mt < 4; mt++) {
        int row0 = bm + wm*64 + mt*16 + g;
        #pragma unroll
        for (int nt = 0; nt < 8; nt++) {
            int col0 = bn + wn*64 + nt*8 + t4*2;
            float b0v = 0.f, b1v = 0.f;
            if (addb) {
                if (col0     < N) b0v = bias[col0];
                if (col0 + 1 < N) b1v = bias[col0+1];
            }
            if (splitk > 1) {
                if (row0 < M) {
                    if (col0     < N) atomicAdd(&C[(size_t)row0*ldc + col0    ], acc[mt][nt][0] + b0v);
                    if (col0 + 1 < N) atomicAdd(&C[(size_t)row0*ldc + col0 + 1], acc[mt][nt][1] + b1v);
                }
                if (row0 + 8 < M) {
                    if (col0     < N) atomicAdd(&C[(size_t)(row0+8)*ldc + col0    ], acc[mt][nt][2] + b0v);
                    if (col0 + 1 < N) atomicAdd(&C[(size_t)(row0+8)*ldc + col0 + 1], acc[mt][nt][3] + b1v);
                }
            } else {
                if (row0 < M) {
                    if (col0     < N) C[(size_t)row0*ldc + col0    ] = acc[mt][nt][0] + b0v;
                    if (col0 + 1 < N) C[(size_t)row0*ldc + col0 + 1] = acc[mt][nt][1] + b1v;
                }
                if (row0 + 8 < M) {
                    if (col0     < N) C[(size_t)(row0+8)*ldc + col0    ] = acc[mt][nt][2] + b0v;
                    if (col0 + 1 < N) C[(size_t)(row0+8)*ldc + col0 + 1] = acc[mt][nt][3] + b1v;
                }
            }
        }
    }
}

// ---------------- fused LSTM step ----------------
__global__ void __launch_bounds__(256)
lstm_step_k(const float* __restrict__ hin,
            float* __restrict__ hout,
            float* __restrict__ cst,
            const float* __restrict__ Xg,
            const float* __restrict__ Whh,
            const float* __restrict__ bhh,
            const int* __restrict__ lengths, int t)
{
    __shared__ float As[8][64];
    __shared__ float Bs[8][64];
    __shared__ float Cs[64][65];
    const int tid = threadIdx.x;
    const int hh0 = blockIdx.x * 16;
    const int bm  = blockIdx.y * 64;
    const int tx = tid & 15, ty = tid >> 4;

    float acc[4][4];
    #pragma unroll
    for (int i = 0; i < 4; i++)
        #pragma unroll
        for (int j = 0; j < 4; j++) acc[i][j] = 0.f;

    for (int k0 = 0; k0 < H_; k0 += 8) {
        if (tid < 128) {
            int m = tid >> 1, kq = (tid & 1)*4;
            float4 v = *reinterpret_cast<const float4*>(hin + (size_t)(bm+m)*H_ + k0 + kq);
            As[kq+0][m]=v.x; As[kq+1][m]=v.y; As[kq+2][m]=v.z; As[kq+3][m]=v.w;
        } else {
            int it = tid - 128;
            int j = it >> 1, kq = (it & 1)*4;
            int gn = (j >> 4)*H_ + hh0 + (j & 15);
            float4 v = *reinterpret_cast<const float4*>(Whh + (size_t)gn*H_ + k0 + kq);
            Bs[kq+0][j]=v.x; Bs[kq+1][j]=v.y; Bs[kq+2][j]=v.z; Bs[kq+3][j]=v.w;
        }
        __syncthreads();
        #pragma unroll
        for (int k = 0; k < 8; k++) {
            float ar[4], br[4];
            #pragma unroll
            for (int i = 0; i < 4; i++) ar[i] = As[k][ty*4+i];
            #pragma unroll
            for (int j = 0; j < 4; j++) br[j] = Bs[k][tx*4+j];
            #pragma unroll
            for (int i = 0; i < 4; i++)
                #pragma unroll
                for (int j = 0; j < 4; j++)
                    acc[i][j] = fmaf(ar[i], br[j], acc[i][j]);
        }
        __syncthreads();
    }
    #pragma unroll
    for (int i = 0; i < 4; i++)
        #pragma unroll
        for (int j = 0; j < 4; j++)
            Cs[ty*4+i][tx*4+j] = acc[i][j];
    __syncthreads();

    #pragma unroll
    for (int i = 0; i < 4; i++) {
        int cell = i*256 + tid;
        int b_l = cell >> 4, hh_l = cell & 15;
        int b = bm + b_l, hh = hh0 + hh_l;
        const float* xrow = Xg + (size_t)(b*L_ + t)*(4*H_);
        float gi = Cs[b_l][0*16+hh_l] + xrow[hh]        + bhh[hh];
        float gf = Cs[b_l][1*16+hh_l] + xrow[H_+hh]     + bhh[H_+hh];
        float gc = Cs[b_l][2*16+hh_l] + xrow[2*H_+hh]   + bhh[2*H_+hh];
        float go = Cs[b_l][3*16+hh_l] + xrow[3*H_+hh]   + bhh[3*H_+hh];
        size_t idx = (size_t)b*H_ + hh;
        float hold = hin[idx];
        if (t < lengths[b]) {
            float cn = sigmoidf_(gf)*cst[idx] + sigmoidf_(gi)*tanhf(gc);
            cst[idx] = cn;
            hout[idx] = sigmoidf_(go)*tanhf(cn);
        } else {
            hout[idx] = hold;
        }
    }
}

// ---------------- fused decoder RNN + attention ----------------
__global__ void __launch_bounds__(256)
dec_attn_k(const float* __restrict__ Q,
           const float* __restrict__ WihT,
           const float* __restrict__ WhhT,
           const float* __restrict__ bih, const float* __restrict__ bhh,
           const float* __restrict__ Vt,
           const int* __restrict__ lengths,
           float* __restrict__ R)
{
    int b = blockIdx.x, tid = threadIdx.x;
    __shared__ float shh[H_], sQ[H_], sh[H_];
    __shared__ float sV[L_][H_];
    __shared__ float sHins[STEPS_][H_];
    __shared__ float satt[STEPS_][L_];

    shh[tid] = Q[(size_t)b*H_ + tid];
    for (int i = tid; i < L_*H_; i += 256) sV[i>>8][i&255] = Vt[(size_t)b*L_*H_ + i];
    __syncthreads();

    float acc = bih[tid];
    #pragma unroll 8
    for (int k = 0; k < H_; k++) acc = fmaf(shh[k], WihT[(size_t)k*H_ + tid], acc);
    sQ[tid] = acc;
    sh[tid] = 0.f;
    __syncthreads();

    for (int s = 0; s < STEPS_; s++) {
        float v = sQ[tid] + bhh[tid];
        #pragma unroll 8
        for (int k = 0; k < H_; k++) v = fmaf(sh[k], WhhT[(size_t)k*H_ + tid], v);
        v = fmaxf(v, 0.f);
        __syncthreads();
        sh[tid] = v;
        sHins[s][tid] = v;
        __syncthreads();
    }

    int warp = tid >> 5, lane = tid & 31;
    for (int pid = warp; pid < STEPS_*L_; pid += 8) {
        int s = pid >> 4, l = pid & 15;
        float a = 0.f;
        #pragma unroll
        for (int q = 0; q < H_/32; q++) a = fmaf(sHins[s][lane+32*q], sV[l][lane+32*q], a);
        a = warp_sum(a);
        if (lane == 0) satt[s][l] = a;
    }
    __syncthreads();
    if (tid < STEPS_) {
        int len = lengths[b];
        float m = -3.4e38f;
        for (int l = 0; l < len; l++) m = fmaxf(m, satt[tid][l]);
        float s = 0.f;
        for (int l = 0; l < len; l++) { float e = expf(satt[tid][l]-m); satt[tid][l]=e; s+=e; }
        float inv = 1.f/s;
        for (int l = 0; l < L_; l++) satt[tid][l] = (l < len) ? satt[tid][l]*inv : 0.f;
    }
    __syncthreads();
    for (int s = 0; s < STEPS_; s++) {
        float a2 = 0.f;
        #pragma unroll
        for (int l = 0; l < L_; l++) a2 = fmaf(satt[s][l], sV[l][tid], a2);
        R[((size_t)b*STEPS_ + s)*H_ + tid] = a2;
    }
}

// ---------------- small kernels ----------------
__global__ void build_c_k(const float* __restrict__ vocab, const float* __restrict__ de,
                          float* __restrict__ Cc) {
    int i = blockIdx.x*256 + threadIdx.x;
    if (i < (V_+1)*H_) Cc[i] = (i < V_*H_) ? vocab[i] : de[i - (size_t)V_*H_];
}

__global__ void transpose_wn_k(const float* __restrict__ W, float* __restrict__ WT) {
    __shared__ float t[32][33];
    int rb = blockIdx.y*32, cb = blockIdx.x*32;
    int x = threadIdx.x, y = threadIdx.y;
    for (int j = y; j < 32; j += 8) t[j][x] = W[(size_t)(rb+j)*H_ + cb + x];
    __syncthreads();
    for (int j = y; j < 32; j += 8) WT[(size_t)(cb+j)*H_ + rb + x] = t[x][j];
}

__global__ void vocab_t_k(const float* __restrict__ vocab, float* __restrict__ vt) {
    __shared__ float t[32][33];
    int vb = blockIdx.x*32, hb = blockIdx.y*32;
    int x = threadIdx.x, y = threadIdx.y;
    for (int j = y; j < 32; j += 8) {
        int v = vb + j;
        t[j][x] = (v < V_) ? vocab[(size_t)v*H_ + hb + x] : 0.f;
    }
    __syncthreads();
    for (int j = y; j < 32; j += 8) {
        int v = vb + x;
        if (v < LDLOG_) vt[(size_t)(hb+j)*LDLOG_ + v] = t[x][j];
    }
}

__global__ void zero_k(float* __restrict__ p, int n) {
    int i = blockIdx.x*256 + threadIdx.x;
    if (i < n) p[i] = 0.f;
}

__global__ void row_softmax_w_k(float* __restrict__ Lg) {
    int r = blockIdx.x;
    float* row = Lg + (size_t)r*LDLOG_;
    __shared__ float red[256];
    float m = -3.4e38f;
    for (int j = threadIdx.x; j < V_+1; j += 256) m = fmaxf(m, row[j]);
    red[threadIdx.x] = m; __syncthreads();
    for (int o = 128; o > 0; o >>= 1) {
        if (threadIdx.x < o) red[threadIdx.x] = fmaxf(red[threadIdx.x], red[threadIdx.x+o]);
        __syncthreads();
    }
    float M = red[0]; __syncthreads();
    float s = 0.f;
    for (int j = threadIdx.x; j < V_+1; j += 256) s += expf(row[j] - M);
    red[threadIdx.x] = s; __syncthreads();
    for (int o = 128; o > 0; o >>= 1) {
        if (threadIdx.x < o) red[threadIdx.x] += red[threadIdx.x+o];
        __syncthreads();
    }
    float inv = 1.f/red[0];
    for (int j = threadIdx.x; j < V_+1; j += 256)
        row[j] = expf(row[j] - M) * inv;
}

__global__ void vtag_eps_k(const float* __restrict__ words, const float* __restrict__ Lg,
                           float* __restrict__ Vt) {
    int i = blockIdx.x*256 + threadIdx.x;
    int r = i >> 8;
    float w = Lg[(size_t)r*LDLOG_ + V_];
    Vt[i] += w * words[i];
}

__global__ void init_dist_k(float* __restrict__ dist) {
    int i = blockIdx.x*256 + threadIdx.x;
    if (i < N_) dist[i] = 1.f/(float)NPG_;
}

#define ZB_ ((N_ + 255)/256)
__global__ void prep_step_k(const float* __restrict__ R, int step,
                            const float* __restrict__ pe, float* __restrict__ ps,
                            float* __restrict__ agg) {
    int bid = blockIdx.x, tid = threadIdx.x;
    if (bid < B_) {
        __shared__ float s4[P_];
        if (tid < 128) {
            int p = tid >> 5, lane = tid & 31;
            const float* instr = R + ((size_t)bid*STEPS_ + step)*H_;
            float acc = 0.f;
            for (int h = lane; h < H_; h += 32) acc = fmaf(instr[h], pe[p*H_ + h], acc);
            acc = warp_sum(acc);
            if (lane == 0) s4[p] = acc;
        }
        __syncthreads();
        if (tid == 0) {
            float m = fmaxf(fmaxf(s4[0], s4[1]), fmaxf(s4[2], s4[3]));
            float e0 = expf(s4[0]-m), e1 = expf(s4[1]-m), e2 = expf(s4[2]-m), e3 = expf(s4[3]-m);
            float inv = 1.f/(e0+e1+e2+e3);
            ps[bid*P_+0]=e0*inv; ps[bid*P_+1]=e1*inv; ps[bid*P_+2]=e2*inv; ps[bid*P_+3]=e3*inv;
        }
    } else {
        int i = (bid - B_)*256 + tid;
        if (i < N_) agg[i] = 0.f;
    }
}

#define NODE_BLKS (N_/8)
#define EDGE_BLKS (E_/8)
__global__ void node_edge_k(const float* __restrict__ Tr, const float* __restrict__ Et,
                            const float* __restrict__ R, int step,
                            const float* __restrict__ ps,
                            const float* __restrict__ Wst, const float* __restrict__ Wrel,
                            const int* __restrict__ ng, const int* __restrict__ eg,
                            const int* __restrict__ esrc, const int* __restrict__ edst,
                            const float* __restrict__ dist,
                            float* __restrict__ nst, float* __restrict__ agg) {
    int bid = blockIdx.x;
    int warp = threadIdx.x >> 5, lane = threadIdx.x & 31;
    if (bid < NODE_BLKS) {
        int n = bid*8 + warp;
        int g = ng[n];
        const float* instr = R + ((size_t)g*STEPS_ + step)*H_;
        float p0 = ps[g*P_+0], p1 = ps[g*P_+1], p2 = ps[g*P_+2];
        const float* T = Tr + (size_t)n*3*H_;
        float acc = 0.f;
        #pragma unroll
        for (int q = 0; q < H_/32; q++) {
            int h = lane + 32*q;
            float tv = p0*T[h] + p1*T[H_+h] + p2*T[2*H_+h];
            float x = instr[h]*tv;
            float e = (x > 0.f) ? x : expm1f(x);
            acc = fmaf(e, Wst[h], acc);
        }
        acc = warp_sum(acc);
        if (lane == 0) nst[n] = acc;
    } else {
        int e = (bid - NODE_BLKS)*8 + warp;
        int g = eg[e];
        const float* instr = R + ((size_t)g*STEPS_ + step)*H_;
        const float* et = Et + (size_t)e*H_;
        float acc = 0.f;
        #pragma unroll
        for (int q = 0; q < H_/32; q++) {
            int h = lane + 32*q;
            float x = instr[h]*et[h];
            float el = (x > 0.f) ? x : expm1f(x);
            acc = fmaf(el, Wrel[h], acc);
        }
        acc = warp_sum(acc);
        if (lane == 0) atomicAdd(&agg[edst[e]], dist[esrc[e]]*acc);
    }
}

__global__ void seg_update_k(const float* __restrict__ nst, const float* __restrict__ agg,
                             const float* __restrict__ ps, float* __restrict__ dist) {
    int g = blockIdx.x, tid = threadIdx.x;
    __shared__ float red[256];
    float v1 = (tid < NPG_) ? nst[g*NPG_ + tid] : -3.4e38f;
    float v2 = (tid < NPG_) ? agg[g*NPG_ + tid] : -3.4e38f;
    red[tid] = v1; __syncthreads();
    for (int o = 128; o > 0; o >>= 1) { if (tid < o) red[tid] = fmaxf(red[tid], red[tid+o]); __syncthreads(); }
    float m1 = red[0]; __syncthreads();
    red[tid] = v2; __syncthreads();
    for (int o = 128; o > 0; o >>= 1) { if (tid < o) red[tid] = fmaxf(red[tid], red[tid+o]); __syncthreads(); }
    float m2 = red[0]; __syncthreads();
    float e1 = (tid < NPG_) ? expf(v1 - m1) : 0.f;
    float e2 = (tid < NPG_) ? expf(v2 - m2) : 0.f;
    red[tid] = e1; __syncthreads();
    for (int o = 128; o > 0; o >>= 1) { if (tid < o) red[tid] += red[tid+o]; __syncthreads(); }
    float s1 = red[0]; __syncthreads();
    red[tid] = e2; __syncthreads();
    for (int o = 128; o > 0; o >>= 1) { if (tid < o) red[tid] += red[tid+o]; __syncthreads(); }
    float s2 = red[0];
    if (tid < NPG_) {
        float r = ps[g*P_ + 3];
        dist[g*NPG_ + tid] = r*(e2/s2) + (1.f - r)*(e1/s1);
    }
}

__global__ void final_agg_qa_k(const float* __restrict__ na, const float* __restrict__ ps,
                               const float* __restrict__ dist, const float* __restrict__ Q,
                               float* __restrict__ QA) {
    int g = blockIdx.x, h = threadIdx.x;
    float p0 = ps[g*P_], p1 = ps[g*P_+1], p2 = ps[g*P_+2];
    float acc = 0.f;
    for (int i = 0; i < NPG_; i++) {
        size_t n = (size_t)g*NPG_ + i;
        const float* a = na + n*3*H_;
        float nf = p0*a[h] + p1*a[H_+h] + p2*a[2*H_+h];
        acc = fmaf(dist[n], nf, acc);
    }
    QA[(size_t)g*2*H_ + h]      = Q[(size_t)g*H_ + h];
    QA[(size_t)g*2*H_ + H_ + h] = acc;
}

// ---------------- launchers ----------------
static inline void tc_gemm(const float* A, int lda, const float* Bm, int ldb,
                           float* C, int ldc, int M, int N, int K,
                           const float* bias, int splitk = 1) {
    dim3 g((N + GB_N - 1)/GB_N, (M + GB_M - 1)/GB_M, splitk);
    mma_gemm_k<<<g, 128, G_SMEM_BYTES>>>(A, lda, Bm, ldb, C, ldc, M, N, K, bias, splitk);
}

extern "C" void kernel_launch(void* const* d_in, const int* in_sizes, int n_in,
                              void* d_out, int out_size) {
    const float* questions     = (const float*)d_in[0];
    const float* node_attrs    = (const float*)d_in[1];
    const float* edge_attrs    = (const float*)d_in[2];
    const float* vocab         = (const float*)d_in[3];
    const float* default_embed = (const float*)d_in[4];
    const float* W_norm        = (const float*)d_in[5];
    const float* lstm_Wih      = (const float*)d_in[6];
    const float* lstm_Whh      = (const float*)d_in[7];
    const float* lstm_bih      = (const float*)d_in[8];
    const float* lstm_bhh      = (const float*)d_in[9];
    const float* rnn_Wih       = (const float*)d_in[10];
    const float* rnn_Whh       = (const float*)d_in[11];
    const float* rnn_bih       = (const float*)d_in[12];
    const float* rnn_bhh       = (const float*)d_in[13];
    const float* prop_embeds   = (const float*)d_in[14];
    const float* Ws_property   = (const float*)d_in[15];
    const float* W_state       = (const float*)d_in[16];
    const float* W_relation    = (const float*)d_in[17];
    const float* lin_W         = (const float*)d_in[18];
    const float* lin_b         = (const float*)d_in[19];
    const int*   lengths       = (const int*)d_in[20];
    const int*   node_graph    = (const int*)d_in[21];
    const int*   edge_graph    = (const int*)d_in[22];
    const int*   edge_src      = (const int*)d_in[23];
    const int*   edge_dst      = (const int*)d_in[24];
    float* out = (float*)d_out;

    cudaFuncSetAttribute(mma_gemm_k, cudaFuncAttributeMaxDynamicSharedMemorySize, G_SMEM_BYTES);

    float* S = nullptr;
    cudaGetSymbolAddress((void**)&S, g_scratch);
    float* Cc   = S + OFF_C;
    float* XW   = S + OFF_XW;
    float* LG   = S + OFF_LOG;
    float* VT   = S + OFF_VT;
    float* XG   = S + OFF_XG;
    float* H0   = S + OFF_H;
    float* Cst  = S + OFF_CS;
    float* H1   = S + OFF_H2;
    float* Rr   = S + OFF_R;
    float* PS   = S + OFF_PS;
    float* TR   = S + OFF_TR;
    float* ET   = S + OFF_ET;
    float* NS   = S + OFF_NS;
    float* AGG  = S + OFF_AGG;
    float* DIST = S + OFF_DIST;
    float* QA   = S + OFF_QA;
    float* WNT  = S + OFF_WNT;
    float* VOCT = S + OFF_VOCT;
    float* WIHT = S + OFF_WIHT;
    float* WHHT = S + OFF_WHHT;

    // 0. one-time layout prep
    build_c_k<<<((V_+1)*H_ + 255)/256, 256>>>(vocab, default_embed, Cc);
    transpose_wn_k<<<dim3(8,8), dim3(32,8)>>>(W_norm, WNT);
    transpose_wn_k<<<dim3(8,8), dim3(32,8)>>>(rnn_Wih, WIHT);
    transpose_wn_k<<<dim3(8,8), dim3(32,8)>>>(rnn_Whh, WHHT);
    vocab_t_k<<<dim3((LDLOG_+31)/32, H_/32), dim3(32,8)>>>(vocab, VOCT);

    // 1. vocab tagging
    tc_gemm(questions, H_, WNT, H_, XW, H_, BL_, H_, H_, nullptr);
    tc_gemm(XW, H_, Cc, H_, LG, LDLOG_, BL_, V_+1, H_, nullptr);
    row_softmax_w_k<<<BL_, 256>>>(LG);
    zero_k<<<(BL_*H_ + 255)/256, 256>>>(VT, BL_*H_);
    tc_gemm(LG, LDLOG_, VOCT, LDLOG_, VT, H_, BL_, H_, V_, nullptr, 4);  // split-K
    vtag_eps_k<<<BL_*H_/256, 256>>>(questions, LG, VT);

    // 2. LSTM encoder
    tc_gemm(VT, H_, lstm_Wih, H_, XG, 4*H_, BL_, 4*H_, H_, lstm_bih);
    zero_k<<<(2*B_*H_ + 255)/256, 256>>>(H0, 2*B_*H_);
    for (int t = 0; t < L_; t++) {
        const float* hin = (t & 1) ? H1 : H0;
        float* hout      = (t & 1) ? H0 : H1;
        lstm_step_k<<<dim3(16,4), 256>>>(hin, hout, Cst, XG, lstm_Whh, lstm_bhh, lengths, t);
    }

    // 3. fused decoder + attention
    dec_attn_k<<<B_, 256>>>(H0, WIHT, WHHT, rnn_bih, rnn_bhh, VT, lengths, Rr);

    // 4. loop-invariant graph transforms
    for (int p = 0; p < 3; p++)
        tc_gemm(node_attrs + p*H_, 3*H_, Ws_property + (size_t)p*H_*H_, H_,
                TR + p*H_, 3*H_, N_, H_, H_, nullptr);
    tc_gemm(edge_attrs, H_, Ws_property + (size_t)3*H_*H_, H_, ET, H_, E_, H_, H_, nullptr);

    init_dist_k<<<(N_ + 255)/256, 256>>>(DIST);

    // 5. 4 reasoning steps
    for (int s = 0; s < STEPS_; s++) {
        prep_step_k<<<B_ + ZB_, 256>>>(Rr, s, prop_embeds, PS, AGG);
        node_edge_k<<<NODE_BLKS + EDGE_BLKS, 256>>>(TR, ET, Rr, s, PS, W_state, W_relation,
                                                    node_graph, edge_graph, edge_src, edge_dst,
                                                    DIST, NS, AGG);
        seg_update_k<<<B_, 256>>>(NS, AGG, PS, DIST);
    }

    // 6. final aggregation + output projection (split-K, pre-zeroed out)
    final_agg_qa_k<<<B_, 256>>>(node_attrs, PS, DIST, H0, QA);
    zero_k<<<(B_*OUT_ + 255)/256, 256>>>(out, B_*OUT_);
    tc_gemm(QA, 2*H_, lin_W, 2*H_, out, OUT_, B_, OUT_, 2*H_, lin_b, 4);
}

// round 8
// speedup vs baseline: 2.7470x; 1.0799x over previous
#include <cuda_runtime.h>
#include <math.h>
#include <stdint.h>

#define B_      256
#define L_      16
#define H_      256
#define V_      5000
#define P_      4
#define NPG_    150
#define DEG_    4
#define EPG_    (NPG_*DEG_)
#define STEPS_  4
#define OUT_    2000
#define N_      (B_*NPG_)
#define E_      (N_*DEG_)
#define BL_     (B_*L_)
#define LDLOG_  5008

// ---------------- scratch arena ----------------
static constexpr size_t SZ_C    = (size_t)(V_+1)*H_;
static constexpr size_t SZ_XW   = (size_t)BL_*H_;
static constexpr size_t SZ_LOG  = (size_t)BL_*LDLOG_;
static constexpr size_t SZ_VT   = (size_t)BL_*H_;
static constexpr size_t SZ_XG   = (size_t)BL_*4*H_;
static constexpr size_t SZ_H    = (size_t)B_*H_;
static constexpr size_t SZ_HINS = (size_t)B_*STEPS_*H_;
static constexpr size_t SZ_TR   = (size_t)N_*3*H_;
static constexpr size_t SZ_ET   = (size_t)E_*H_;

static constexpr size_t OFF_C    = 0;
static constexpr size_t OFF_XW   = OFF_C    + SZ_C;
static constexpr size_t OFF_LOG  = OFF_XW   + SZ_XW;
static constexpr size_t OFF_VT   = OFF_LOG  + SZ_LOG;
static constexpr size_t OFF_XG   = OFF_VT   + SZ_VT;
static constexpr size_t OFF_H    = OFF_XG   + SZ_XG;
static constexpr size_t OFF_CS   = OFF_H    + SZ_H;
static constexpr size_t OFF_H2   = OFF_CS   + SZ_H;
static constexpr size_t OFF_R    = OFF_H2   + SZ_H;
static constexpr size_t OFF_PS   = OFF_R    + SZ_HINS;                      // [B][STEPS][P]
static constexpr size_t OFF_TR   = OFF_PS   + (size_t)B_*STEPS_*P_;
static constexpr size_t OFF_ET   = OFF_TR   + SZ_TR;
static constexpr size_t OFF_NS4  = OFF_ET   + SZ_ET;                        // [N][4]
static constexpr size_t OFF_ES4  = OFF_NS4  + (size_t)N_*4;                 // [E][4]
static constexpr size_t OFF_DIST = OFF_ES4  + (size_t)E_*4;
static constexpr size_t OFF_QA   = OFF_DIST + N_;
static constexpr size_t OFF_WNT  = OFF_QA   + (size_t)B_*2*H_;
static constexpr size_t OFF_VOCT = OFF_WNT  + (size_t)H_*H_;
static constexpr size_t OFF_WIHT = OFF_VOCT + (size_t)H_*LDLOG_;
static constexpr size_t OFF_WHHT = OFF_WIHT + (size_t)H_*H_;
static constexpr size_t TOTAL_SCRATCH = OFF_WHHT + (size_t)H_*H_;

__device__ __align__(16) float g_scratch[TOTAL_SCRATCH];

// ---------------- helpers ----------------
__device__ __forceinline__ float warp_sum(float v) {
    #pragma unroll
    for (int o = 16; o > 0; o >>= 1) v += __shfl_down_sync(0xffffffffu, v, o);
    return v;
}
__device__ __forceinline__ float sigmoidf_(float x) { return 1.f / (1.f + expf(-x)); }
__device__ __forceinline__ uint32_t f2tf32(float x) {
    uint32_t u;
    asm("cvt.rna.tf32.f32 %0, %1;" : "=r"(u) : "f"(x));
    return u;
}
__device__ __forceinline__ uint32_t smem_u32(const void* p) {
    uint32_t a;
    asm("{ .reg .u64 t; cvta.to.shared.u64 t, %1; cvt.u32.u64 %0, t; }" : "=r"(a) : "l"(p));
    return a;
}
__device__ __forceinline__ void cp_async16(void* sdst, const void* gsrc, bool pred) {
    uint32_t d = smem_u32(sdst);
    int sz = pred ? 16 : 0;
    asm volatile("cp.async.cg.shared.global [%0], [%1], 16, %2;"
                 :: "r"(d), "l"(gsrc), "r"(sz));
}
__device__ __forceinline__ void cp_commit() {
    asm volatile("cp.async.commit_group;" ::: "memory");
}
template<int N>
__device__ __forceinline__ void cp_wait() {
    asm volatile("cp.async.wait_group %0;" :: "n"(N) : "memory");
}
__device__ __forceinline__ void mma_tf32(float* d, const uint32_t* a, const uint32_t* b) {
    asm volatile(
        "mma.sync.aligned.m16n8k8.row.col.f32.tf32.tf32.f32 "
        "{%0,%1,%2,%3}, {%4,%5,%6,%7}, {%8,%9}, {%0,%1,%2,%3};"
        : "+f"(d[0]), "+f"(d[1]), "+f"(d[2]), "+f"(d[3])
        : "r"(a[0]), "r"(a[1]), "r"(a[2]), "r"(a[3]), "r"(b[0]), "r"(b[1]));
}

// ---------------- tensor-core tf32 GEMM: CTA 128x128x32, warp 64x64 ----------------
#define GB_M 128
#define GB_N 128
#define GB_K 32
#define GTS  36
#define GABUF (GB_M*GTS)
#define GBBUF (GB_N*GTS)
#define G_SMEM_BYTES ((2*GABUF + 2*GBBUF)*4)

__global__ void __launch_bounds__(128, 2)
mma_gemm_k(const float* __restrict__ A, int lda,
           const float* __restrict__ Bm, int ldb,
           float* __restrict__ C, int ldc,
           int M, int N, int K, const float* __restrict__ bias, int splitk)
{
    extern __shared__ float smf[];
    float* As = smf;
    float* Bs = smf + 2*GABUF;
    const int tid  = threadIdx.x;
    const int wid  = tid >> 5, lane = tid & 31;
    const int g    = lane >> 2, t4 = lane & 3;
    const int wm   = wid & 1, wn = wid >> 1;
    const int bm   = blockIdx.y * GB_M;
    const int bn   = blockIdx.x * GB_N;

    int kslen = K, kbeg = 0, kend = K;
    if (splitk > 1) {
        kslen = (((K + splitk - 1) / splitk) + 3) & ~3;
        kbeg  = blockIdx.z * kslen;
        kend  = min(K, kbeg + kslen);
    }

    float acc[4][8][4];
    #pragma unroll
    for (int i = 0; i < 4; i++)
        #pragma unroll
        for (int j = 0; j < 8; j++)
            #pragma unroll
            for (int q = 0; q < 4; q++) acc[i][j][q] = 0.f;

    const int lrow = tid >> 3, lc4 = (tid & 7) << 2;

    auto issue_chunk = [&](int c) {
        int k0 = kbeg + c * GB_K;
        int buf = c & 1;
        #pragma unroll
        for (int i = 0; i < 8; i++) {
            int row = lrow + i*16;
            int gm = bm + row, gk = k0 + lc4;
            cp_async16(As + buf*GABUF + row*GTS + lc4,
                       A + (size_t)gm*lda + gk, (gm < M) && (gk < kend));
        }
        #pragma unroll
        for (int i = 0; i < 8; i++) {
            int row = lrow + i*16;
            int gn = bn + row, gk = k0 + lc4;
            cp_async16(Bs + buf*GBBUF + row*GTS + lc4,
                       Bm + (size_t)gn*ldb + gk, (gn < N) && (gk < kend));
        }
        cp_commit();
    };

    const int nch = (kend - kbeg + GB_K - 1) / GB_K;
    issue_chunk(0);

    for (int c = 0; c < nch; c++) {
        if (c + 1 < nch) { issue_chunk(c + 1); cp_wait<1>(); }
        else             { cp_wait<0>(); }
        __syncthreads();

        const float* Ab = As + (c & 1)*GABUF;
        const float* Bb = Bs + (c & 1)*GBBUF;
        #pragma unroll
        for (int ks = 0; ks < 4; ks++) {
            uint32_t af[4][4], bf[8][2];
            #pragma unroll
            for (int mt = 0; mt < 4; mt++) {
                int r0 = (wm*64 + mt*16 + g)*GTS + ks*8 + t4;
                af[mt][0] = f2tf32(Ab[r0]);
                af[mt][1] = f2tf32(Ab[r0 + 8*GTS]);
                af[mt][2] = f2tf32(Ab[r0 + 4]);
                af[mt][3] = f2tf32(Ab[r0 + 8*GTS + 4]);
            }
            #pragma unroll
            for (int nt = 0; nt < 8; nt++) {
                int rb = (wn*64 + nt*8 + g)*GTS + ks*8 + t4;
                bf[nt][0] = f2tf32(Bb[rb]);
                bf[nt][1] = f2tf32(Bb[rb + 4]);
            }
            #pragma unroll
            for (int mt = 0; mt < 4; mt++)
                #pragma unroll
                for (int nt = 0; nt < 8; nt++)
                    mma_tf32(acc[mt][nt], af[mt], bf[nt]);
        }
        __syncthreads();
    }

    const bool addb = (bias != nullptr) && (blockIdx.z == 0);
    #pragma unroll
    for (int mt = 0; mt < 4; mt++) {
        int row0 = bm + wm*64 + mt*16 + g;
        #pragma unroll
        for (int nt = 0; nt < 8; nt++) {
            int col0 = bn + wn*64 + nt*8 + t4*2;
            float b0v = 0.f, b1v = 0.f;
            if (addb) {
                if (col0     < N) b0v = bias[col0];
                if (col0 + 1 < N) b1v = bias[col0+1];
            }
            if (splitk > 1) {
                if (row0 < M) {
                    if (col0     < N) atomicAdd(&C[(size_t)row0*ldc + col0    ], acc[mt][nt][0] + b0v);
                    if (col0 + 1 < N) atomicAdd(&C[(size_t)row0*ldc + col0 + 1], acc[mt][nt][1] + b1v);
                }
                if (row0 + 8 < M) {
                    if (col0     < N) atomicAdd(&C[(size_t)(row0+8)*ldc + col0    ], acc[mt][nt][2] + b0v);
                    if (col0 + 1 < N) atomicAdd(&C[(size_t)(row0+8)*ldc + col0 + 1], acc[mt][nt][3] + b1v);
                }
            } else {
                if (row0 < M) {
                    if (col0     < N) C[(size_t)row0*ldc + col0    ] = acc[mt][nt][0] + b0v;
                    if (col0 + 1 < N) C[(size_t)row0*ldc + col0 + 1] = acc[mt][nt][1] + b1v;
                }
                if (row0 + 8 < M) {
                    if (col0     < N) C[(size_t)(row0+8)*ldc + col0    ] = acc[mt][nt][2] + b0v;
                    if (col0 + 1 < N) C[(size_t)(row0+8)*ldc + col0 + 1] = acc[mt][nt][3] + b1v;
                }
            }
        }
    }
}

// ---------------- fused LSTM step ----------------
__global__ void __launch_bounds__(256)
lstm_step_k(const float* __restrict__ hin,
            float* __restrict__ hout,
            float* __restrict__ cst,
            const float* __restrict__ Xg,
            const float* __restrict__ Whh,
            const float* __restrict__ bhh,
            const int* __restrict__ lengths, int t)
{
    __shared__ float As[8][64];
    __shared__ float Bs[8][64];
    __shared__ float Cs[64][65];
    const int tid = threadIdx.x;
    const int hh0 = blockIdx.x * 16;
    const int bm  = blockIdx.y * 64;
    const int tx = tid & 15, ty = tid >> 4;

    float acc[4][4];
    #pragma unroll
    for (int i = 0; i < 4; i++)
        #pragma unroll
        for (int j = 0; j < 4; j++) acc[i][j] = 0.f;

    for (int k0 = 0; k0 < H_; k0 += 8) {
        if (tid < 128) {
            int m = tid >> 1, kq = (tid & 1)*4;
            float4 v = *reinterpret_cast<const float4*>(hin + (size_t)(bm+m)*H_ + k0 + kq);
            As[kq+0][m]=v.x; As[kq+1][m]=v.y; As[kq+2][m]=v.z; As[kq+3][m]=v.w;
        } else {
            int it = tid - 128;
            int j = it >> 1, kq = (it & 1)*4;
            int gn = (j >> 4)*H_ + hh0 + (j & 15);
            float4 v = *reinterpret_cast<const float4*>(Whh + (size_t)gn*H_ + k0 + kq);
            Bs[kq+0][j]=v.x; Bs[kq+1][j]=v.y; Bs[kq+2][j]=v.z; Bs[kq+3][j]=v.w;
        }
        __syncthreads();
        #pragma unroll
        for (int k = 0; k < 8; k++) {
            float ar[4], br[4];
            #pragma unroll
            for (int i = 0; i < 4; i++) ar[i] = As[k][ty*4+i];
            #pragma unroll
            for (int j = 0; j < 4; j++) br[j] = Bs[k][tx*4+j];
            #pragma unroll
            for (int i = 0; i < 4; i++)
                #pragma unroll
                for (int j = 0; j < 4; j++)
                    acc[i][j] = fmaf(ar[i], br[j], acc[i][j]);
        }
        __syncthreads();
    }
    #pragma unroll
    for (int i = 0; i < 4; i++)
        #pragma unroll
        for (int j = 0; j < 4; j++)
            Cs[ty*4+i][tx*4+j] = acc[i][j];
    __syncthreads();

    #pragma unroll
    for (int i = 0; i < 4; i++) {
        int cell = i*256 + tid;
        int b_l = cell >> 4, hh_l = cell & 15;
        int b = bm + b_l, hh = hh0 + hh_l;
        const float* xrow = Xg + (size_t)(b*L_ + t)*(4*H_);
        float gi = Cs[b_l][0*16+hh_l] + xrow[hh]        + bhh[hh];
        float gf = Cs[b_l][1*16+hh_l] + xrow[H_+hh]     + bhh[H_+hh];
        float gc = Cs[b_l][2*16+hh_l] + xrow[2*H_+hh]   + bhh[2*H_+hh];
        float go = Cs[b_l][3*16+hh_l] + xrow[3*H_+hh]   + bhh[3*H_+hh];
        size_t idx = (size_t)b*H_ + hh;
        float hold = hin[idx];
        if (t < lengths[b]) {
            float cn = sigmoidf_(gf)*cst[idx] + sigmoidf_(gi)*tanhf(gc);
            cst[idx] = cn;
            hout[idx] = sigmoidf_(go)*tanhf(cn);
        } else {
            hout[idx] = hold;
        }
    }
}

// ---------------- fused decoder RNN + attention ----------------
__global__ void __launch_bounds__(256)
dec_attn_k(const float* __restrict__ Q,
           const float* __restrict__ WihT,
           const float* __restrict__ WhhT,
           const float* __restrict__ bih, const float* __restrict__ bhh,
           const float* __restrict__ Vt,
           const int* __restrict__ lengths,
           float* __restrict__ R)
{
    int b = blockIdx.x, tid = threadIdx.x;
    __shared__ float shh[H_], sQ[H_], sh[H_];
    __shared__ float sV[L_][H_];
    __shared__ float sHins[STEPS_][H_];
    __shared__ float satt[STEPS_][L_];

    shh[tid] = Q[(size_t)b*H_ + tid];
    for (int i = tid; i < L_*H_; i += 256) sV[i>>8][i&255] = Vt[(size_t)b*L_*H_ + i];
    __syncthreads();

    float acc = bih[tid];
    #pragma unroll 8
    for (int k = 0; k < H_; k++) acc = fmaf(shh[k], WihT[(size_t)k*H_ + tid], acc);
    sQ[tid] = acc;
    sh[tid] = 0.f;
    __syncthreads();

    for (int s = 0; s < STEPS_; s++) {
        float v = sQ[tid] + bhh[tid];
        #pragma unroll 8
        for (int k = 0; k < H_; k++) v = fmaf(sh[k], WhhT[(size_t)k*H_ + tid], v);
        v = fmaxf(v, 0.f);
        __syncthreads();
        sh[tid] = v;
        sHins[s][tid] = v;
        __syncthreads();
    }

    int warp = tid >> 5, lane = tid & 31;
    for (int pid = warp; pid < STEPS_*L_; pid += 8) {
        int s = pid >> 4, l = pid & 15;
        float a = 0.f;
        #pragma unroll
        for (int q = 0; q < H_/32; q++) a = fmaf(sHins[s][lane+32*q], sV[l][lane+32*q], a);
        a = warp_sum(a);
        if (lane == 0) satt[s][l] = a;
    }
    __syncthreads();
    if (tid < STEPS_) {
        int len = lengths[b];
        float m = -3.4e38f;
        for (int l = 0; l < len; l++) m = fmaxf(m, satt[tid][l]);
        float s = 0.f;
        for (int l = 0; l < len; l++) { float e = expf(satt[tid][l]-m); satt[tid][l]=e; s+=e; }
        float inv = 1.f/s;
        for (int l = 0; l < L_; l++) satt[tid][l] = (l < len) ? satt[tid][l]*inv : 0.f;
    }
    __syncthreads();
    for (int s = 0; s < STEPS_; s++) {
        float a2 = 0.f;
        #pragma unroll
        for (int l = 0; l < L_; l++) a2 = fmaf(satt[s][l], sV[l][tid], a2);
        R[((size_t)b*STEPS_ + s)*H_ + tid] = a2;
    }
}

// ---------------- small kernels ----------------
__global__ void build_c_k(const float* __restrict__ vocab, const float* __restrict__ de,
                          float* __restrict__ Cc) {
    int i = blockIdx.x*256 + threadIdx.x;
    if (i < (V_+1)*H_) Cc[i] = (i < V_*H_) ? vocab[i] : de[i - (size_t)V_*H_];
}

__global__ void transpose_wn_k(const float* __restrict__ W, float* __restrict__ WT) {
    __shared__ float t[32][33];
    int rb = blockIdx.y*32, cb = blockIdx.x*32;
    int x = threadIdx.x, y = threadIdx.y;
    for (int j = y; j < 32; j += 8) t[j][x] = W[(size_t)(rb+j)*H_ + cb + x];
    __syncthreads();
    for (int j = y; j < 32; j += 8) WT[(size_t)(cb+j)*H_ + rb + x] = t[x][j];
}

__global__ void vocab_t_k(const float* __restrict__ vocab, float* __restrict__ vt) {
    __shared__ float t[32][33];
    int vb = blockIdx.x*32, hb = blockIdx.y*32;
    int x = threadIdx.x, y = threadIdx.y;
    for (int j = y; j < 32; j += 8) {
        int v = vb + j;
        t[j][x] = (v < V_) ? vocab[(size_t)v*H_ + hb + x] : 0.f;
    }
    __syncthreads();
    for (int j = y; j < 32; j += 8) {
        int v = vb + x;
        if (v < LDLOG_) vt[(size_t)(hb+j)*LDLOG_ + v] = t[x][j];
    }
}

__global__ void zero_k(float* __restrict__ p, int n) {
    int i = blockIdx.x*256 + threadIdx.x;
    if (i < n) p[i] = 0.f;
}

__global__ void row_softmax_w_k(float* __restrict__ Lg) {
    int r = blockIdx.x;
    float* row = Lg + (size_t)r*LDLOG_;
    __shared__ float red[256];
    float m = -3.4e38f;
    for (int j = threadIdx.x; j < V_+1; j += 256) m = fmaxf(m, row[j]);
    red[threadIdx.x] = m; __syncthreads();
    for (int o = 128; o > 0; o >>= 1) {
        if (threadIdx.x < o) red[threadIdx.x] = fmaxf(red[threadIdx.x], red[threadIdx.x+o]);
        __syncthreads();
    }
    float M = red[0]; __syncthreads();
    float s = 0.f;
    for (int j = threadIdx.x; j < V_+1; j += 256) s += expf(row[j] - M);
    red[threadIdx.x] = s; __syncthreads();
    for (int o = 128; o > 0; o >>= 1) {
        if (threadIdx.x < o) red[threadIdx.x] += red[threadIdx.x+o];
        __syncthreads();
    }
    float inv = 1.f/red[0];
    for (int j = threadIdx.x; j < V_+1; j += 256)
        row[j] = expf(row[j] - M) * inv;
}

__global__ void vtag_eps_k(const float* __restrict__ words, const float* __restrict__ Lg,
                           float* __restrict__ Vt) {
    int i = blockIdx.x*256 + threadIdx.x;
    int r = i >> 8;
    float w = Lg[(size_t)r*LDLOG_ + V_];
    Vt[i] += w * words[i];
}

// ---- prop softmax for ALL steps upfront: PS4[b][s][P] ----
__global__ void __launch_bounds__(128)
prop_all_k(const float* __restrict__ R, const float* __restrict__ pe,
           float* __restrict__ ps4) {
    int b = blockIdx.x, s = blockIdx.y;
    int p = threadIdx.x >> 5, lane = threadIdx.x & 31;
    const float* instr = R + ((size_t)b*STEPS_ + s)*H_;
    float acc = 0.f;
    for (int h = lane; h < H_; h += 32) acc = fmaf(instr[h], pe[p*H_ + h], acc);
    acc = warp_sum(acc);
    __shared__ float s4[P_];
    if (lane == 0) s4[p] = acc;
    __syncthreads();
    if (threadIdx.x == 0) {
        float m = fmaxf(fmaxf(s4[0], s4[1]), fmaxf(s4[2], s4[3]));
        float e0 = expf(s4[0]-m), e1 = expf(s4[1]-m), e2 = expf(s4[2]-m), e3 = expf(s4[3]-m);
        float inv = 1.f/(e0+e1+e2+e3);
        float* o = ps4 + ((size_t)b*STEPS_ + s)*P_;
        o[0]=e0*inv; o[1]=e1*inv; o[2]=e2*inv; o[3]=e3*inv;
    }
}

// ---- one-pass scores for all 4 steps: NS4[n][4], ES4[e][4] ----
#define NODE_BLKS (N_/8)
#define EDGE_BLKS (E_/8)
__global__ void __launch_bounds__(256)
scores_k(const float* __restrict__ Tr, const float* __restrict__ Et,
         const float* __restrict__ R, const float* __restrict__ ps4,
         const float* __restrict__ Wst, const float* __restrict__ Wrel,
         const int* __restrict__ ng, const int* __restrict__ eg,
         float* __restrict__ ns4, float* __restrict__ es4) {
    int bid = blockIdx.x;
    int warp = threadIdx.x >> 5, lane = threadIdx.x & 31;
    if (bid < NODE_BLKS) {
        int n = bid*8 + warp;
        int g = ng[n];
        const float* T = Tr + (size_t)n*3*H_;
        float t0[8], t1[8], t2[8], ws[8];
        #pragma unroll
        for (int q = 0; q < 8; q++) {
            int h = lane + 32*q;
            t0[q] = T[h]; t1[q] = T[H_+h]; t2[q] = T[2*H_+h]; ws[q] = Wst[h];
        }
        float out[STEPS_];
        #pragma unroll
        for (int s = 0; s < STEPS_; s++) {
            const float* pp = ps4 + ((size_t)g*STEPS_ + s)*P_;
            float p0 = pp[0], p1 = pp[1], p2 = pp[2];
            const float* instr = R + ((size_t)g*STEPS_ + s)*H_;
            float acc = 0.f;
            #pragma unroll
            for (int q = 0; q < 8; q++) {
                int h = lane + 32*q;
                float tv = p0*t0[q] + p1*t1[q] + p2*t2[q];
                float x = instr[h]*tv;
                float e = (x > 0.f) ? x : expm1f(x);
                acc = fmaf(e, ws[q], acc);
            }
            out[s] = warp_sum(acc);
        }
        if (lane == 0)
            *reinterpret_cast<float4*>(ns4 + (size_t)n*4) =
                make_float4(out[0], out[1], out[2], out[3]);
    } else {
        int e = (bid - NODE_BLKS)*8 + warp;
        int g = eg[e];
        const float* et = Et + (size_t)e*H_;
        float ev[8], wr[8];
        #pragma unroll
        for (int q = 0; q < 8; q++) {
            int h = lane + 32*q;
            ev[q] = et[h]; wr[q] = Wrel[h];
        }
        float out[STEPS_];
        #pragma unroll
        for (int s = 0; s < STEPS_; s++) {
            const float* instr = R + ((size_t)g*STEPS_ + s)*H_;
            float acc = 0.f;
            #pragma unroll
            for (int q = 0; q < 8; q++) {
                int h = lane + 32*q;
                float x = instr[h]*ev[q];
                float el = (x > 0.f) ? x : expm1f(x);
                acc = fmaf(el, wr[q], acc);
            }
            out[s] = warp_sum(acc);
        }
        if (lane == 0)
            *reinterpret_cast<float4*>(es4 + (size_t)e*4) =
                make_float4(out[0], out[1], out[2], out[3]);
    }
}

// ---- full 4-step dist recurrence: one block per graph, all in SMEM ----
__global__ void __launch_bounds__(256)
graph_loop_k(const float* __restrict__ ns4, const float* __restrict__ es4,
             const float* __restrict__ ps4,
             const int* __restrict__ esrc, const int* __restrict__ edst,
             float* __restrict__ dist_out) {
    int g = blockIdx.x, tid = threadIdx.x;
    __shared__ float dist[NPG_], agg[NPG_], red[256];
    __shared__ int lsrc[EPG_], ldst[EPG_];
    __shared__ float4 ns[NPG_];

    int nbase = g*NPG_, ebase = g*EPG_;
    for (int e = tid; e < EPG_; e += 256) {
        lsrc[e] = esrc[ebase + e] - nbase;
        ldst[e] = edst[ebase + e] - nbase;
    }
    if (tid < NPG_) {
        dist[tid] = 1.f/(float)NPG_;
        ns[tid] = *reinterpret_cast<const float4*>(ns4 + (size_t)(nbase + tid)*4);
    }
    __syncthreads();

    for (int s = 0; s < STEPS_; s++) {
        if (tid < NPG_) agg[tid] = 0.f;
        __syncthreads();
        for (int e = tid; e < EPG_; e += 256) {
            float sc = es4[(size_t)(ebase + e)*4 + s];
            atomicAdd(&agg[ldst[e]], dist[lsrc[e]]*sc);
        }
        __syncthreads();

        float nsv = (tid < NPG_) ? ((const float*)&ns[tid])[s] : -3.4e38f;
        float agv = (tid < NPG_) ? agg[tid] : -3.4e38f;
        red[tid] = nsv; __syncthreads();
        for (int o = 128; o > 0; o >>= 1) { if (tid < o) red[tid] = fmaxf(red[tid], red[tid+o]); __syncthreads(); }
        float m1 = red[0]; __syncthreads();
        red[tid] = agv; __syncthreads();
        for (int o = 128; o > 0; o >>= 1) { if (tid < o) red[tid] = fmaxf(red[tid], red[tid+o]); __syncthreads(); }
        float m2 = red[0]; __syncthreads();
        float e1 = (tid < NPG_) ? expf(nsv - m1) : 0.f;
        float e2 = (tid < NPG_) ? expf(agv - m2) : 0.f;
        red[tid] = e1; __syncthreads();
        for (int o = 128; o > 0; o >>= 1) { if (tid < o) red[tid] += red[tid+o]; __syncthreads(); }
        float s1 = red[0]; __syncthreads();
        red[tid] = e2; __syncthreads();
        for (int o = 128; o > 0; o >>= 1) { if (tid < o) red[tid] += red[tid+o]; __syncthreads(); }
        float s2 = red[0]; __syncthreads();
        if (tid < NPG_) {
            float r = ps4[((size_t)g*STEPS_ + s)*P_ + 3];
            dist[tid] = r*(e2/s2) + (1.f - r)*(e1/s1);
        }
        __syncthreads();
    }
    if (tid < NPG_) dist_out[nbase + tid] = dist[tid];
}

__global__ void final_agg_qa_k(const float* __restrict__ na, const float* __restrict__ ps4,
                               const float* __restrict__ dist, const float* __restrict__ Q,
                               float* __restrict__ QA) {
    int g = blockIdx.x, h = threadIdx.x;
    const float* pp = ps4 + ((size_t)g*STEPS_ + (STEPS_-1))*P_;
    float p0 = pp[0], p1 = pp[1], p2 = pp[2];
    float acc = 0.f;
    for (int i = 0; i < NPG_; i++) {
        size_t n = (size_t)g*NPG_ + i;
        const float* a = na + n*3*H_;
        float nf = p0*a[h] + p1*a[H_+h] + p2*a[2*H_+h];
        acc = fmaf(dist[n], nf, acc);
    }
    QA[(size_t)g*2*H_ + h]      = Q[(size_t)g*H_ + h];
    QA[(size_t)g*2*H_ + H_ + h] = acc;
}

// ---------------- launchers ----------------
static inline void tc_gemm(const float* A, int lda, const float* Bm, int ldb,
                           float* C, int ldc, int M, int N, int K,
                           const float* bias, int splitk = 1) {
    dim3 g((N + GB_N - 1)/GB_N, (M + GB_M - 1)/GB_M, splitk);
    mma_gemm_k<<<g, 128, G_SMEM_BYTES>>>(A, lda, Bm, ldb, C, ldc, M, N, K, bias, splitk);
}

extern "C" void kernel_launch(void* const* d_in, const int* in_sizes, int n_in,
                              void* d_out, int out_size) {
    const float* questions     = (const float*)d_in[0];
    const float* node_attrs    = (const float*)d_in[1];
    const float* edge_attrs    = (const float*)d_in[2];
    const float* vocab         = (const float*)d_in[3];
    const float* default_embed = (const float*)d_in[4];
    const float* W_norm        = (const float*)d_in[5];
    const float* lstm_Wih      = (const float*)d_in[6];
    const float* lstm_Whh      = (const float*)d_in[7];
    const float* lstm_bih      = (const float*)d_in[8];
    const float* lstm_bhh      = (const float*)d_in[9];
    const float* rnn_Wih       = (const float*)d_in[10];
    const float* rnn_Whh       = (const float*)d_in[11];
    const float* rnn_bih       = (const float*)d_in[12];
    const float* rnn_bhh       = (const float*)d_in[13];
    const float* prop_embeds   = (const float*)d_in[14];
    const float* Ws_property   = (const float*)d_in[15];
    const float* W_state       = (const float*)d_in[16];
    const float* W_relation    = (const float*)d_in[17];
    const float* lin_W         = (const float*)d_in[18];
    const float* lin_b         = (const float*)d_in[19];
    const int*   lengths       = (const int*)d_in[20];
    const int*   node_graph    = (const int*)d_in[21];
    const int*   edge_graph    = (const int*)d_in[22];
    const int*   edge_src      = (const int*)d_in[23];
    const int*   edge_dst      = (const int*)d_in[24];
    float* out = (float*)d_out;

    cudaFuncSetAttribute(mma_gemm_k, cudaFuncAttributeMaxDynamicSharedMemorySize, G_SMEM_BYTES);

    float* S = nullptr;
    cudaGetSymbolAddress((void**)&S, g_scratch);
    float* Cc   = S + OFF_C;
    float* XW   = S + OFF_XW;
    float* LG   = S + OFF_LOG;
    float* VT   = S + OFF_VT;
    float* XG   = S + OFF_XG;
    float* H0   = S + OFF_H;
    float* Cst  = S + OFF_CS;
    float* H1   = S + OFF_H2;
    float* Rr   = S + OFF_R;
    float* PS4  = S + OFF_PS;
    float* TR   = S + OFF_TR;
    float* ET   = S + OFF_ET;
    float* NS4  = S + OFF_NS4;
    float* ES4  = S + OFF_ES4;
    float* DIST = S + OFF_DIST;
    float* QA   = S + OFF_QA;
    float* WNT  = S + OFF_WNT;
    float* VOCT = S + OFF_VOCT;
    float* WIHT = S + OFF_WIHT;
    float* WHHT = S + OFF_WHHT;

    // 0. one-time layout prep
    build_c_k<<<((V_+1)*H_ + 255)/256, 256>>>(vocab, default_embed, Cc);
    transpose_wn_k<<<dim3(8,8), dim3(32,8)>>>(W_norm, WNT);
    transpose_wn_k<<<dim3(8,8), dim3(32,8)>>>(rnn_Wih, WIHT);
    transpose_wn_k<<<dim3(8,8), dim3(32,8)>>>(rnn_Whh, WHHT);
    vocab_t_k<<<dim3((LDLOG_+31)/32, H_/32), dim3(32,8)>>>(vocab, VOCT);

    // 1. vocab tagging
    tc_gemm(questions, H_, WNT, H_, XW, H_, BL_, H_, H_, nullptr);
    tc_gemm(XW, H_, Cc, H_, LG, LDLOG_, BL_, V_+1, H_, nullptr);
    row_softmax_w_k<<<BL_, 256>>>(LG);
    zero_k<<<(BL_*H_ + 255)/256, 256>>>(VT, BL_*H_);
    tc_gemm(LG, LDLOG_, VOCT, LDLOG_, VT, H_, BL_, H_, V_, nullptr, 4);
    vtag_eps_k<<<BL_*H_/256, 256>>>(questions, LG, VT);

    // 2. LSTM encoder
    tc_gemm(VT, H_, lstm_Wih, H_, XG, 4*H_, BL_, 4*H_, H_, lstm_bih);
    zero_k<<<(2*B_*H_ + 255)/256, 256>>>(H0, 2*B_*H_);
    for (int t = 0; t < L_; t++) {
        const float* hin = (t & 1) ? H1 : H0;
        float* hout      = (t & 1) ? H0 : H1;
        lstm_step_k<<<dim3(16,4), 256>>>(hin, hout, Cst, XG, lstm_Whh, lstm_bhh, lengths, t);
    }

    // 3. fused decoder + attention
    dec_attn_k<<<B_, 256>>>(H0, WIHT, WHHT, rnn_bih, rnn_bhh, VT, lengths, Rr);

    // 4. loop-invariant graph transforms
    for (int p = 0; p < 3; p++)
        tc_gemm(node_attrs + p*H_, 3*H_, Ws_property + (size_t)p*H_*H_, H_,
                TR + p*H_, 3*H_, N_, H_, H_, nullptr);
    tc_gemm(edge_attrs, H_, Ws_property + (size_t)3*H_*H_, H_, ET, H_, E_, H_, H_, nullptr);

    // 5. reasoning: PS for all steps -> one-pass scores -> per-graph SMEM loop
    prop_all_k<<<dim3(B_, STEPS_), 128>>>(Rr, prop_embeds, PS4);
    scores_k<<<NODE_BLKS + EDGE_BLKS, 256>>>(TR, ET, Rr, PS4, W_state, W_relation,
                                             node_graph, edge_graph, NS4, ES4);
    graph_loop_k<<<B_, 256>>>(NS4, ES4, PS4, edge_src, edge_dst, DIST);

    // 6. final aggregation + output projection
    final_agg_qa_k<<<B_, 256>>>(node_attrs, PS4, DIST, H0, QA);
    zero_k<<<(B_*OUT_ + 255)/256, 256>>>(out, B_*OUT_);
    tc_gemm(QA, 2*H_, lin_W, 2*H_, out, OUT_, B_, OUT_, 2*H_, lin_b, 4);
}